// round 8
// baseline (speedup 1.0000x reference)
#include <cuda_runtime.h>
#include <cuda_fp16.h>
#include <math.h>
#include <stdint.h>

#define DD 64
#define CC 256
#define RR 128
#define NPTS 100000
#define VV (DD*DD*DD)

// ---------------- scratch (static device globals; no allocations) ----------
__device__ int     g_idx  [VV];               // [x][y][z] -> point or -1
__device__ int     g_idx_t[VV];               // [z][x*64+y] -> point or -1
// z-passed grid, layout [z][cs][xy][8 half2]  (cs = channel slice of 16 ch)
__device__ __half2 g_h1[(size_t)VV * 128];
__device__ __half2 g_y [(size_t)NPTS * 128];  // gathered pooled features

#define SWS    264                 // sW1T [128 n][264] half
#define SW2S_H 136                 // sW2T [256 n][136] half
__device__ __align__(16) __half g_w1p[RR*SWS];     // prepacked W1^T, padded
__device__ __align__(16) __half g_w2p[CC*SW2S_H];  // prepacked W2^T, padded

#define NEGINF (-INFINITY)

// ---------------- index grids + weight prepack ------------------------------
__global__ void k_init_idx() {
    int i = blockIdx.x * blockDim.x + threadIdx.x;
    if (i < VV) { g_idx[i] = -1; g_idx_t[i] = -1; }
}

__global__ void k_scatter(const int* __restrict__ coords) {
    int i = blockIdx.x * blockDim.x + threadIdx.x;
    if (i < NPTS) {
        int ix = coords[3*i], iy = coords[3*i+1], iz = coords[3*i+2];
        g_idx  [(ix*DD + iy)*DD + iz] = i;
        g_idx_t[iz*4096 + ix*DD + iy] = i;
    }
}

__global__ void k_prepack(const float* __restrict__ W1, const float* __restrict__ W2) {
    int i = blockIdx.x * blockDim.x + threadIdx.x;   // 0..32767
    { int k = i >> 7, n = i & 127; g_w1p[n*SWS    + k] = __float2half(W1[i]); }
    { int k = i >> 8, n = i & 255; g_w2p[n*SW2S_H + k] = __float2half(W2[i]); }
}

// ---------------- helpers ---------------------------------------------------
#define SHIFT1(w, v) do { w[6]=w[5]; w[5]=w[4]; w[4]=w[3]; w[3]=w[2]; w[2]=w[1]; w[1]=w[0]; w[0]=(v); } while(0)
__device__ __forceinline__ __half2 max7h(const __half2* w) {
    return __hmax2(__hmax2(__hmax2(w[0],w[1]),__hmax2(w[2],w[3])),
                   __hmax2(__hmax2(w[4],w[5]),w[6]));
}

// ---------------- z-pass: 4 channels/thread, LDG.128 + STG.64 ---------------
// grid: 128 column-blocks (32 cols) x 16 channel slices = 2048 CTAs, 128 thr.
__global__ __launch_bounds__(128) void k_pool_z(const float* __restrict__ feats) {
    int cb = blockIdx.x >> 4;          // column block: columns cb*32 .. +31
    int cs = blockIdx.x & 15;          // channel slice (16 ch)
    int cl = threadIdx.x >> 2;         // 0..31 column within block
    int cg = threadIdx.x & 3;          // 4-channel group within slice

    __shared__ int pid[32*DD];
    #pragma unroll
    for (int k = 0; k < 16; k++)
        pid[threadIdx.x + 128*k] = g_idx[cb*2048 + threadIdx.x + 128*k];
    __syncthreads();

    const __half2 NEG2 = __float2half2_rn(NEGINF);
    __half2 wa[7], wb[7];
    #pragma unroll
    for (int i = 0; i < 7; i++) { wa[i] = NEG2; wb[i] = NEG2; }

    const int xy = cb*32 + cl;
    // fbase4 + p*64 == &feats[p*256 + cs*16 + cg*4]
    const float4* fbase4 = (const float4*)(feats + cs*16 + cg*4);

    #pragma unroll
    for (int zz = 0; zz < 3; zz++) {
        int p = pid[cl*DD + zz];
        __half2 va = NEG2, vb = NEG2;
        if (p >= 0) {
            float4 f = fbase4[(size_t)p*64];
            va = __floats2half2_rn(f.x, f.y);
            vb = __floats2half2_rn(f.z, f.w);
        }
        SHIFT1(wa, va); SHIFT1(wb, vb);
    }
    #pragma unroll 4
    for (int z = 0; z < DD; z++) {
        int zz = z + 3;
        __half2 va = NEG2, vb = NEG2;
        if (zz < DD) {
            int p = pid[cl*DD + zz];
            if (p >= 0) {
                float4 f = fbase4[(size_t)p*64];
                va = __floats2half2_rn(f.x, f.y);
                vb = __floats2half2_rn(f.z, f.w);
            }
        }
        SHIFT1(wa, va); SHIFT1(wb, vb);
        __half2 o0 = max7h(wa), o1 = max7h(wb);
        uint2 ov; ov.x = *(unsigned*)&o0; ov.y = *(unsigned*)&o1;
        *(uint2*)&g_h1[((size_t)(z*16 + cs)*4096 + xy)*8 + cg*2] = ov;
    }
}

// ---------------- fused y-pass + x-pass + gather (512 threads) --------------
#define TXS 520                                    // words per x row
#define YX_SMEM_BYTES ((64*TXS + 4096) * 4)        // 149504

__global__ __launch_bounds__(512) void k_pool_yx() {
    extern __shared__ unsigned smw[];
    unsigned* sT  = smw;                 // tile, word = half2
    int*      spid = (int*)(smw + 64*TXS);

    int z  = blockIdx.x >> 4;
    int cs = blockIdx.x & 15;
    int tid = threadIdx.x;

    const uint4* src = (const uint4*)(g_h1 + (size_t)(z*16 + cs)*32768);
    #pragma unroll
    for (int k = 0; k < 16; k++) {
        int q = tid + 512*k;
        uint4 v = src[q];
        int w0 = q*4;
        int xy = w0 >> 3, c0 = w0 & 7;
        *(uint4*)&sT[(xy>>6)*TXS + (xy&63)*8 + c0] = v;
    }
    {
        const uint4* isrc = (const uint4*)(g_idx_t + z*4096);
        #pragma unroll
        for (int k = 0; k < 2; k++)
            *(uint4*)&spid[(tid + 512*k)*4] = isrc[tid + 512*k];
    }
    __syncthreads();

    const __half2 NEG2 = __float2half2_rn(NEGINF);

    {   // y-pass, in-place
        int x = tid >> 3, c = tid & 7;
        unsigned* col = sT + x*TXS + c;
        __half2 w[7];
        #pragma unroll
        for (int i = 0; i < 7; i++) w[i] = NEG2;
        #pragma unroll
        for (int yy = 0; yy < 3; yy++) { unsigned r = col[yy*8]; SHIFT1(w, *(__half2*)&r); }
        #pragma unroll 4
        for (int y = 0; y < DD; y++) {
            int yy = y + 3;
            __half2 v = NEG2;
            if (yy < DD) { unsigned r = col[yy*8]; v = *(__half2*)&r; }
            SHIFT1(w, v);
            __half2 o = max7h(w);
            col[y*8] = *(unsigned*)&o;
        }
    }
    __syncthreads();

    {   // x-pass + sparse gather
        int y = tid >> 3, c = tid & 7;
        unsigned* col = sT + y*8 + c;
        __half2 w[7];
        #pragma unroll
        for (int i = 0; i < 7; i++) w[i] = NEG2;
        #pragma unroll
        for (int xx = 0; xx < 3; xx++) { unsigned r = col[xx*TXS]; SHIFT1(w, *(__half2*)&r); }
        #pragma unroll 4
        for (int x = 0; x < DD; x++) {
            int xx = x + 3;
            __half2 v = NEG2;
            if (xx < DD) { unsigned r = col[xx*TXS]; v = *(__half2*)&r; }
            SHIFT1(w, v);
            int p = spid[x*64 + y];
            if (p >= 0) g_y[(size_t)p*128 + cs*8 + c] = max7h(w);
        }
    }
}

// ---------------- fused MLP (8Mx2N warps, ldmatrix A+B) ---------------------
// fp16 mma m16n8k16; 512 threads = 16 warps; 256 rows/CTA.

__device__ __forceinline__ uint32_t s2u(const void* p) {
    return (uint32_t)__cvta_generic_to_shared(p);
}
__device__ __forceinline__ void ldmA(uint32_t* a, const void* p) {
    asm volatile("ldmatrix.sync.aligned.m8n8.x4.shared.b16 {%0,%1,%2,%3}, [%4];"
        : "=r"(a[0]),"=r"(a[1]),"=r"(a[2]),"=r"(a[3]) : "r"(s2u(p)));
}
__device__ __forceinline__ void ldmB4(uint32_t* b, uint32_t saddr) {
    asm volatile("ldmatrix.sync.aligned.m8n8.x4.shared.b16 {%0,%1,%2,%3}, [%4];"
        : "=r"(b[0]),"=r"(b[1]),"=r"(b[2]),"=r"(b[3]) : "r"(saddr));
}
__device__ __forceinline__ void mma16(float* d, const uint32_t* a, const uint32_t* b,
                                      const float* c) {
    asm volatile("mma.sync.aligned.m16n8k16.row.col.f32.f16.f16.f32 "
        "{%0,%1,%2,%3}, {%4,%5,%6,%7}, {%8,%9}, {%10,%11,%12,%13};"
        : "=f"(d[0]),"=f"(d[1]),"=f"(d[2]),"=f"(d[3])
        : "r"(a[0]),"r"(a[1]),"r"(a[2]),"r"(a[3]),
          "r"(b[0]),"r"(b[1]),
          "f"(c[0]),"f"(c[1]),"f"(c[2]),"f"(c[3]));
}

#define SAS 264                     // sA [256 m][264] half (also sH region)
#define SHS_H 136                   // sH [256 m][136] half (inside sA region)
#define AW_HALFS (256*SAS)          // 67584 halfs = 135168 B
#define MLP_SMEM_BYTES (AW_HALFS*2 + 256*SW2S_H*2)   // 204800

__global__ __launch_bounds__(512, 1) void k_mlp(
    const float* __restrict__ feats, float* __restrict__ out) {
    extern __shared__ __half smh[];
    __half* sA  = smh;                       // phase A: A tile; phase B: sH
    __half* sW  = smh + AW_HALFS;            // phase A: W1T; phase B: W2T
    __half* sH  = smh;

    int tid = threadIdx.x;
    int lane = tid & 31, wid = tid >> 5;
    int group = lane >> 2, tg = lane & 3;
    int warpM = wid & 7, warpN = wid >> 3;   // 8 x 2
    int rowbase = warpM * 32;
    int colbase = warpN * 64;
    int m0 = blockIdx.x * 256;

    // ldmatrix-B per-lane tile addressing
    int bg = lane >> 3, br = lane & 7;
    int b_nt_off = (bg >> 1);                // 0/1 : which nt within the pair
    int b_k_off  = (bg & 1) * 8;             // 0/8 : k half

    // stage A tile (256 rows x 256 halfs) from g_y with uint4 loads
    {
        const __half* Yh = (const __half*)g_y;
        #pragma unroll
        for (int k = 0; k < 16; k++) {
            int u = tid + 512*k;             // uint4 index, 8192 total
            int row = u >> 5, cw = (u & 31)*8;
            int gr = m0 + row; if (gr >= NPTS) gr = NPTS - 1;
            uint4 v = *(const uint4*)(Yh + (size_t)gr*CC + cw);
            *(uint4*)&sA[row*SAS + cw] = v;
        }
    }
    // stage prepacked W1T: 4224 uint4
    {
        const uint4* wsrc = (const uint4*)g_w1p;
        uint4* wdst = (uint4*)sW;
        #pragma unroll
        for (int k = 0; k < 9; k++) {
            int u = tid + 512*k;
            if (u < (RR*SWS)/8) wdst[u] = wsrc[u];
        }
    }
    __syncthreads();

    // ---- GEMM1: H[256][128] = A @ W1 ----
    int lrow = lane & 15;
    int lk   = (lane >> 4) * 8;
    {
        uint32_t bp[4];
        #pragma unroll
        for (int j = 0; j < 4; j++)
            bp[j] = s2u(&sW[(colbase + (2*j + b_nt_off)*8 + br)*SWS + b_k_off]);

        float acc[2][8][4];
        #pragma unroll
        for (int mt = 0; mt < 2; mt++)
            #pragma unroll
            for (int nt = 0; nt < 8; nt++)
                #pragma unroll
                for (int q = 0; q < 4; q++) acc[mt][nt][q] = 0.f;

        for (int k0 = 0; k0 < CC; k0 += 16) {
            uint32_t a[2][4];
            #pragma unroll
            for (int mt = 0; mt < 2; mt++)
                ldmA(a[mt], &sA[(rowbase + mt*16 + lrow)*SAS + k0 + lk]);
            uint32_t b[8][2];
            #pragma unroll
            for (int j = 0; j < 4; j++) {
                uint32_t bb[4];
                ldmB4(bb, bp[j] + k0*2);
                b[2*j][0]   = bb[0]; b[2*j][1]   = bb[1];
                b[2*j+1][0] = bb[2]; b[2*j+1][1] = bb[3];
            }
            #pragma unroll
            for (int mt = 0; mt < 2; mt++)
                #pragma unroll
                for (int nt = 0; nt < 8; nt++)
                    mma16(acc[mt][nt], a[mt], b[nt], acc[mt][nt]);
        }
        __syncthreads();   // everyone done reading sA / sW

        // relu -> sH (fp16, reuses sA region)
        #pragma unroll
        for (int mt = 0; mt < 2; mt++)
            #pragma unroll
            for (int nt = 0; nt < 8; nt++) {
                int rl = rowbase + mt*16 + group;
                int cl = colbase + nt*8 + 2*tg;
                __half2 h0 = __floats2half2_rn(fmaxf(acc[mt][nt][0],0.f),
                                               fmaxf(acc[mt][nt][1],0.f));
                __half2 h1 = __floats2half2_rn(fmaxf(acc[mt][nt][2],0.f),
                                               fmaxf(acc[mt][nt][3],0.f));
                *(__half2*)&sH[rl*SHS_H + cl]     = h0;
                *(__half2*)&sH[(rl+8)*SHS_H + cl] = h1;
            }
    }
    // stage prepacked W2T: 4352 uint4
    {
        const uint4* wsrc = (const uint4*)g_w2p;
        uint4* wdst = (uint4*)sW;
        #pragma unroll
        for (int k = 0; k < 9; k++) {
            int u = tid + 512*k;
            if (u < (CC*SW2S_H)/8) wdst[u] = wsrc[u];
        }
    }
    __syncthreads();

    // ---- GEMM2: Z = H @ W2, two 64-col passes per warp ----
    for (int p = 0; p < 2; p++) {
        int cb = warpN*128 + p*64;
        uint32_t bp[4];
        #pragma unroll
        for (int j = 0; j < 4; j++)
            bp[j] = s2u(&sW[(cb + (2*j + b_nt_off)*8 + br)*SW2S_H + b_k_off]);

        float acc2[2][8][4];
        #pragma unroll
        for (int mt = 0; mt < 2; mt++)
            #pragma unroll
            for (int nt = 0; nt < 8; nt++)
                #pragma unroll
                for (int q = 0; q < 4; q++) acc2[mt][nt][q] = 0.f;

        for (int k0 = 0; k0 < RR; k0 += 16) {
            uint32_t a[2][4];
            #pragma unroll
            for (int mt = 0; mt < 2; mt++)
                ldmA(a[mt], &sH[(rowbase + mt*16 + lrow)*SHS_H + k0 + lk]);
            uint32_t b[8][2];
            #pragma unroll
            for (int j = 0; j < 4; j++) {
                uint32_t bb[4];
                ldmB4(bb, bp[j] + k0*2);
                b[2*j][0]   = bb[0]; b[2*j][1]   = bb[1];
                b[2*j+1][0] = bb[2]; b[2*j+1][1] = bb[3];
            }
            #pragma unroll
            for (int mt = 0; mt < 2; mt++)
                #pragma unroll
                for (int nt = 0; nt < 8; nt++)
                    mma16(acc2[mt][nt], a[mt], b[nt], acc2[mt][nt]);
        }

        // epilogue: sigmoid, multiply feats, store
        #pragma unroll
        for (int mt = 0; mt < 2; mt++)
            #pragma unroll
            for (int nt = 0; nt < 8; nt++) {
                int rl = rowbase + mt*16 + group;
                int cl = cb + nt*8 + 2*tg;
                int gi0 = m0 + rl, gi1 = gi0 + 8;
                if (gi0 < NPTS) {
                    float2 f = *(const float2*)(feats + (size_t)gi0*CC + cl);
                    float s0 = 1.f/(1.f + __expf(-acc2[mt][nt][0]));
                    float s1 = 1.f/(1.f + __expf(-acc2[mt][nt][1]));
                    float2 o; o.x = f.x*s0; o.y = f.y*s1;
                    *(float2*)(out + (size_t)gi0*CC + cl) = o;
                }
                if (gi1 < NPTS) {
                    float2 f = *(const float2*)(feats + (size_t)gi1*CC + cl);
                    float s2 = 1.f/(1.f + __expf(-acc2[mt][nt][2]));
                    float s3 = 1.f/(1.f + __expf(-acc2[mt][nt][3]));
                    float2 o; o.x = f.x*s2; o.y = f.y*s3;
                    *(float2*)(out + (size_t)gi1*CC + cl) = o;
                }
            }
    }
}

// ---------------- launch ----------------------------------------------------
extern "C" void kernel_launch(void* const* d_in, const int* in_sizes, int n_in,
                              void* d_out, int out_size) {
    const float* feats  = (const float*)d_in[0];
    const int*   coords = (const int*)d_in[1];
    const float* W1     = (const float*)d_in[2];
    const float* W2     = (const float*)d_in[3];
    float*       out    = (float*)d_out;

    k_prepack<<<128, 256>>>(W1, W2);
    k_init_idx<<<(VV + 255)/256, 256>>>();
    k_scatter<<<(NPTS + 255)/256, 256>>>(coords);
    k_pool_z<<<2048, 128>>>(feats);

    cudaFuncSetAttribute(k_pool_yx, cudaFuncAttributeMaxDynamicSharedMemorySize,
                         YX_SMEM_BYTES);
    k_pool_yx<<<1024, 512, YX_SMEM_BYTES>>>();

    cudaFuncSetAttribute(k_mlp, cudaFuncAttributeMaxDynamicSharedMemorySize,
                         MLP_SMEM_BYTES);
    int nblk = (NPTS + 255) / 256;   // 391
    k_mlp<<<nblk, 512, MLP_SMEM_BYTES>>>(feats, out);
}

// round 9
// speedup vs baseline: 1.1190x; 1.1190x over previous
#include <cuda_runtime.h>
#include <cuda_fp16.h>
#include <math.h>
#include <stdint.h>

#define DD 64
#define CC 256
#define RR 128
#define NPTS 100000
#define VV (DD*DD*DD)

// ---------------- scratch (static device globals; no allocations) ----------
__device__ int     g_idx  [VV];               // [x][y][z] -> point or -1
__device__ int     g_idx_t[VV];               // [z][x*64+y] -> point or -1
// z-passed grid, layout [z][cs][xy][8 half2]  (cs = channel slice of 16 ch)
__device__ __half2 g_h1[(size_t)VV * 128];
__device__ __half2 g_y [(size_t)NPTS * 128];  // gathered pooled features

#define SWS    264                 // sW1T [128 n][264] half
#define SW2S_H 136                 // sW2T [256 n][136] half
__device__ __align__(16) __half g_w1p[RR*SWS];     // prepacked W1^T, padded
__device__ __align__(16) __half g_w2p[CC*SW2S_H];  // prepacked W2^T, padded

#define NEGINF (-INFINITY)

// ---------------- index grids + weight prepack ------------------------------
__global__ void k_init_idx() {
    int i = blockIdx.x * blockDim.x + threadIdx.x;
    if (i < VV) { g_idx[i] = -1; g_idx_t[i] = -1; }
}

__global__ void k_scatter(const int* __restrict__ coords) {
    int i = blockIdx.x * blockDim.x + threadIdx.x;
    if (i < NPTS) {
        int ix = coords[3*i], iy = coords[3*i+1], iz = coords[3*i+2];
        g_idx  [(ix*DD + iy)*DD + iz] = i;
        g_idx_t[iz*4096 + ix*DD + iy] = i;
    }
}

__global__ void k_prepack(const float* __restrict__ W1, const float* __restrict__ W2) {
    int i = blockIdx.x * blockDim.x + threadIdx.x;   // 0..32767
    { int k = i >> 7, n = i & 127; g_w1p[n*SWS    + k] = __float2half(W1[i]); }
    { int k = i >> 8, n = i & 255; g_w2p[n*SW2S_H + k] = __float2half(W2[i]); }
}

// ---------------- helpers ---------------------------------------------------
#define SHIFT1(w, v) do { w[6]=w[5]; w[5]=w[4]; w[4]=w[3]; w[3]=w[2]; w[2]=w[1]; w[1]=w[0]; w[0]=(v); } while(0)
__device__ __forceinline__ __half2 max7h(const __half2* w) {
    return __hmax2(__hmax2(__hmax2(w[0],w[1]),__hmax2(w[2],w[3])),
                   __hmax2(__hmax2(w[4],w[5]),w[6]));
}

// ---------------- z-pass: round-7 shape + distance-2 prefetch ---------------
// grid: 128 column-blocks (32 cols) x 16 channel slices = 2048 CTAs, 256 thr.
__global__ __launch_bounds__(256) void k_pool_z(const float* __restrict__ feats) {
    int cb = blockIdx.x >> 4;          // column block: columns cb*32 .. +31
    int cs = blockIdx.x & 15;          // channel slice (16 ch = 8 half2)
    int cl = threadIdx.x >> 3;         // 0..31 column within block
    int c  = threadIdx.x & 7;          // half2 within slice

    __shared__ int pid[32*DD];
    #pragma unroll
    for (int k = 0; k < 8; k++)
        pid[threadIdx.x + 256*k] = g_idx[cb*2048 + threadIdx.x + 256*k];
    __syncthreads();

    const __half2 NEG2 = __float2half2_rn(NEGINF);
    __half2 w[7];
    #pragma unroll
    for (int i = 0; i < 7; i++) w[i] = NEG2;

    const int xy = cb*32 + cl;
    const float* fbase = feats + cs*16 + c*2;
    const int* mypid = pid + cl*DD;

    // warm the pipeline: taps 0 and 1
    float2 fA = make_float2(NEGINF, NEGINF);
    float2 fB = make_float2(NEGINF, NEGINF);
    { int p = mypid[0]; if (p >= 0) fA = *(const float2*)(fbase + (size_t)p*CC); }
    { int p = mypid[1]; if (p >= 0) fB = *(const float2*)(fbase + (size_t)p*CC); }

    // tap loop: t = 0..66; consume tap t, prefetch tap t+2
    #pragma unroll 4
    for (int t = 0; t < DD + 3; t++) {
        float2 cur = fA;
        fA = fB;
        fB = make_float2(NEGINF, NEGINF);
        int tn = t + 2;
        if (tn < DD) {
            int p = mypid[tn];
            if (p >= 0) fB = *(const float2*)(fbase + (size_t)p*CC);
        }
        SHIFT1(w, __floats2half2_rn(cur.x, cur.y));
        if (t >= 3) {
            int z = t - 3;
            g_h1[((size_t)(z*16 + cs)*4096 + xy)*8 + c] = max7h(w);
        }
    }
}

// ---------------- fused y-pass + x-pass + gather (512 threads) --------------
#define TXS 520                                    // words per x row
#define YX_SMEM_BYTES ((64*TXS + 4096) * 4)        // 149504

__global__ __launch_bounds__(512) void k_pool_yx() {
    extern __shared__ unsigned smw[];
    unsigned* sT  = smw;                 // tile, word = half2
    int*      spid = (int*)(smw + 64*TXS);

    int z  = blockIdx.x >> 4;
    int cs = blockIdx.x & 15;
    int tid = threadIdx.x;

    const uint4* src = (const uint4*)(g_h1 + (size_t)(z*16 + cs)*32768);
    #pragma unroll
    for (int k = 0; k < 16; k++) {
        int q = tid + 512*k;
        uint4 v = src[q];
        int w0 = q*4;
        int xy = w0 >> 3, c0 = w0 & 7;
        *(uint4*)&sT[(xy>>6)*TXS + (xy&63)*8 + c0] = v;
    }
    {
        const uint4* isrc = (const uint4*)(g_idx_t + z*4096);
        #pragma unroll
        for (int k = 0; k < 2; k++)
            *(uint4*)&spid[(tid + 512*k)*4] = isrc[tid + 512*k];
    }
    __syncthreads();

    const __half2 NEG2 = __float2half2_rn(NEGINF);

    {   // y-pass, in-place
        int x = tid >> 3, c = tid & 7;
        unsigned* col = sT + x*TXS + c;
        __half2 w[7];
        #pragma unroll
        for (int i = 0; i < 7; i++) w[i] = NEG2;
        #pragma unroll
        for (int yy = 0; yy < 3; yy++) { unsigned r = col[yy*8]; SHIFT1(w, *(__half2*)&r); }
        #pragma unroll 4
        for (int y = 0; y < DD; y++) {
            int yy = y + 3;
            __half2 v = NEG2;
            if (yy < DD) { unsigned r = col[yy*8]; v = *(__half2*)&r; }
            SHIFT1(w, v);
            __half2 o = max7h(w);
            col[y*8] = *(unsigned*)&o;
        }
    }
    __syncthreads();

    {   // x-pass + sparse gather
        int y = tid >> 3, c = tid & 7;
        unsigned* col = sT + y*8 + c;
        __half2 w[7];
        #pragma unroll
        for (int i = 0; i < 7; i++) w[i] = NEG2;
        #pragma unroll
        for (int xx = 0; xx < 3; xx++) { unsigned r = col[xx*TXS]; SHIFT1(w, *(__half2*)&r); }
        #pragma unroll 4
        for (int x = 0; x < DD; x++) {
            int xx = x + 3;
            __half2 v = NEG2;
            if (xx < DD) { unsigned r = col[xx*TXS]; v = *(__half2*)&r; }
            SHIFT1(w, v);
            int p = spid[x*64 + y];
            if (p >= 0) g_y[(size_t)p*128 + cs*8 + c] = max7h(w);
        }
    }
}

// ---------------- fused MLP (8Mx2N warps, ldmatrix A+B) ---------------------
// fp16 mma m16n8k16; 512 threads = 16 warps; 256 rows/CTA.

__device__ __forceinline__ uint32_t s2u(const void* p) {
    return (uint32_t)__cvta_generic_to_shared(p);
}
__device__ __forceinline__ void ldmA(uint32_t* a, const void* p) {
    asm volatile("ldmatrix.sync.aligned.m8n8.x4.shared.b16 {%0,%1,%2,%3}, [%4];"
        : "=r"(a[0]),"=r"(a[1]),"=r"(a[2]),"=r"(a[3]) : "r"(s2u(p)));
}
__device__ __forceinline__ void ldmB4(uint32_t* b, uint32_t saddr) {
    asm volatile("ldmatrix.sync.aligned.m8n8.x4.shared.b16 {%0,%1,%2,%3}, [%4];"
        : "=r"(b[0]),"=r"(b[1]),"=r"(b[2]),"=r"(b[3]) : "r"(saddr));
}
__device__ __forceinline__ void mma16(float* d, const uint32_t* a, const uint32_t* b,
                                      const float* c) {
    asm volatile("mma.sync.aligned.m16n8k16.row.col.f32.f16.f16.f32 "
        "{%0,%1,%2,%3}, {%4,%5,%6,%7}, {%8,%9}, {%10,%11,%12,%13};"
        : "=f"(d[0]),"=f"(d[1]),"=f"(d[2]),"=f"(d[3])
        : "r"(a[0]),"r"(a[1]),"r"(a[2]),"r"(a[3]),
          "r"(b[0]),"r"(b[1]),
          "f"(c[0]),"f"(c[1]),"f"(c[2]),"f"(c[3]));
}

#define SAS 264                     // sA [256 m][264] half (also sH region)
#define SHS_H 136                   // sH [256 m][136] half (inside sA region)
#define AW_HALFS (256*SAS)          // 67584 halfs = 135168 B
#define MLP_SMEM_BYTES (AW_HALFS*2 + 256*SW2S_H*2)   // 204800

__global__ __launch_bounds__(512, 1) void k_mlp(
    const float* __restrict__ feats, float* __restrict__ out) {
    extern __shared__ __half smh[];
    __half* sA  = smh;                       // phase A: A tile; phase B: sH
    __half* sW  = smh + AW_HALFS;            // phase A: W1T; phase B: W2T
    __half* sH  = smh;

    int tid = threadIdx.x;
    int lane = tid & 31, wid = tid >> 5;
    int group = lane >> 2, tg = lane & 3;
    int warpM = wid & 7, warpN = wid >> 3;   // 8 x 2
    int rowbase = warpM * 32;
    int colbase = warpN * 64;
    int m0 = blockIdx.x * 256;

    // ldmatrix-B per-lane tile addressing
    int bg = lane >> 3, br = lane & 7;
    int b_nt_off = (bg >> 1);                // 0/1 : which nt within the pair
    int b_k_off  = (bg & 1) * 8;             // 0/8 : k half

    // stage A tile (256 rows x 256 halfs) from g_y with uint4 loads
    {
        const __half* Yh = (const __half*)g_y;
        #pragma unroll
        for (int k = 0; k < 16; k++) {
            int u = tid + 512*k;             // uint4 index, 8192 total
            int row = u >> 5, cw = (u & 31)*8;
            int gr = m0 + row; if (gr >= NPTS) gr = NPTS - 1;
            uint4 v = *(const uint4*)(Yh + (size_t)gr*CC + cw);
            *(uint4*)&sA[row*SAS + cw] = v;
        }
    }
    // stage prepacked W1T: 4224 uint4
    {
        const uint4* wsrc = (const uint4*)g_w1p;
        uint4* wdst = (uint4*)sW;
        #pragma unroll
        for (int k = 0; k < 9; k++) {
            int u = tid + 512*k;
            if (u < (RR*SWS)/8) wdst[u] = wsrc[u];
        }
    }
    __syncthreads();

    // ---- GEMM1: H[256][128] = A @ W1 ----
    int lrow = lane & 15;
    int lk   = (lane >> 4) * 8;
    {
        uint32_t bp[4];
        #pragma unroll
        for (int j = 0; j < 4; j++)
            bp[j] = s2u(&sW[(colbase + (2*j + b_nt_off)*8 + br)*SWS + b_k_off]);

        float acc[2][8][4];
        #pragma unroll
        for (int mt = 0; mt < 2; mt++)
            #pragma unroll
            for (int nt = 0; nt < 8; nt++)
                #pragma unroll
                for (int q = 0; q < 4; q++) acc[mt][nt][q] = 0.f;

        for (int k0 = 0; k0 < CC; k0 += 16) {
            uint32_t a[2][4];
            #pragma unroll
            for (int mt = 0; mt < 2; mt++)
                ldmA(a[mt], &sA[(rowbase + mt*16 + lrow)*SAS + k0 + lk]);
            uint32_t b[8][2];
            #pragma unroll
            for (int j = 0; j < 4; j++) {
                uint32_t bb[4];
                ldmB4(bb, bp[j] + k0*2);
                b[2*j][0]   = bb[0]; b[2*j][1]   = bb[1];
                b[2*j+1][0] = bb[2]; b[2*j+1][1] = bb[3];
            }
            #pragma unroll
            for (int mt = 0; mt < 2; mt++)
                #pragma unroll
                for (int nt = 0; nt < 8; nt++)
                    mma16(acc[mt][nt], a[mt], b[nt], acc[mt][nt]);
        }
        __syncthreads();   // everyone done reading sA / sW

        // relu -> sH (fp16, reuses sA region)
        #pragma unroll
        for (int mt = 0; mt < 2; mt++)
            #pragma unroll
            for (int nt = 0; nt < 8; nt++) {
                int rl = rowbase + mt*16 + group;
                int cl = colbase + nt*8 + 2*tg;
                __half2 h0 = __floats2half2_rn(fmaxf(acc[mt][nt][0],0.f),
                                               fmaxf(acc[mt][nt][1],0.f));
                __half2 h1 = __floats2half2_rn(fmaxf(acc[mt][nt][2],0.f),
                                               fmaxf(acc[mt][nt][3],0.f));
                *(__half2*)&sH[rl*SHS_H + cl]     = h0;
                *(__half2*)&sH[(rl+8)*SHS_H + cl] = h1;
            }
    }
    // stage prepacked W2T: 4352 uint4
    {
        const uint4* wsrc = (const uint4*)g_w2p;
        uint4* wdst = (uint4*)sW;
        #pragma unroll
        for (int k = 0; k < 9; k++) {
            int u = tid + 512*k;
            if (u < (CC*SW2S_H)/8) wdst[u] = wsrc[u];
        }
    }
    __syncthreads();

    // ---- GEMM2: Z = H @ W2, two 64-col passes per warp ----
    for (int p = 0; p < 2; p++) {
        int cb = warpN*128 + p*64;
        uint32_t bp[4];
        #pragma unroll
        for (int j = 0; j < 4; j++)
            bp[j] = s2u(&sW[(cb + (2*j + b_nt_off)*8 + br)*SW2S_H + b_k_off]);

        float acc2[2][8][4];
        #pragma unroll
        for (int mt = 0; mt < 2; mt++)
            #pragma unroll
            for (int nt = 0; nt < 8; nt++)
                #pragma unroll
                for (int q = 0; q < 4; q++) acc2[mt][nt][q] = 0.f;

        for (int k0 = 0; k0 < RR; k0 += 16) {
            uint32_t a[2][4];
            #pragma unroll
            for (int mt = 0; mt < 2; mt++)
                ldmA(a[mt], &sH[(rowbase + mt*16 + lrow)*SHS_H + k0 + lk]);
            uint32_t b[8][2];
            #pragma unroll
            for (int j = 0; j < 4; j++) {
                uint32_t bb[4];
                ldmB4(bb, bp[j] + k0*2);
                b[2*j][0]   = bb[0]; b[2*j][1]   = bb[1];
                b[2*j+1][0] = bb[2]; b[2*j+1][1] = bb[3];
            }
            #pragma unroll
            for (int mt = 0; mt < 2; mt++)
                #pragma unroll
                for (int nt = 0; nt < 8; nt++)
                    mma16(acc2[mt][nt], a[mt], b[nt], acc2[mt][nt]);
        }

        // epilogue: sigmoid, multiply feats, store
        #pragma unroll
        for (int mt = 0; mt < 2; mt++)
            #pragma unroll
            for (int nt = 0; nt < 8; nt++) {
                int rl = rowbase + mt*16 + group;
                int cl = cb + nt*8 + 2*tg;
                int gi0 = m0 + rl, gi1 = gi0 + 8;
                if (gi0 < NPTS) {
                    float2 f = *(const float2*)(feats + (size_t)gi0*CC + cl);
                    float s0 = 1.f/(1.f + __expf(-acc2[mt][nt][0]));
                    float s1 = 1.f/(1.f + __expf(-acc2[mt][nt][1]));
                    float2 o; o.x = f.x*s0; o.y = f.y*s1;
                    *(float2*)(out + (size_t)gi0*CC + cl) = o;
                }
                if (gi1 < NPTS) {
                    float2 f = *(const float2*)(feats + (size_t)gi1*CC + cl);
                    float s2 = 1.f/(1.f + __expf(-acc2[mt][nt][2]));
                    float s3 = 1.f/(1.f + __expf(-acc2[mt][nt][3]));
                    float2 o; o.x = f.x*s2; o.y = f.y*s3;
                    *(float2*)(out + (size_t)gi1*CC + cl) = o;
                }
            }
    }
}

// ---------------- launch ----------------------------------------------------
extern "C" void kernel_launch(void* const* d_in, const int* in_sizes, int n_in,
                              void* d_out, int out_size) {
    const float* feats  = (const float*)d_in[0];
    const int*   coords = (const int*)d_in[1];
    const float* W1     = (const float*)d_in[2];
    const float* W2     = (const float*)d_in[3];
    float*       out    = (float*)d_out;

    k_prepack<<<128, 256>>>(W1, W2);
    k_init_idx<<<(VV + 255)/256, 256>>>();
    k_scatter<<<(NPTS + 255)/256, 256>>>(coords);
    k_pool_z<<<2048, 256>>>(feats);

    cudaFuncSetAttribute(k_pool_yx, cudaFuncAttributeMaxDynamicSharedMemorySize,
                         YX_SMEM_BYTES);
    k_pool_yx<<<1024, 512, YX_SMEM_BYTES>>>();

    cudaFuncSetAttribute(k_mlp, cudaFuncAttributeMaxDynamicSharedMemorySize,
                         MLP_SMEM_BYTES);
    int nblk = (NPTS + 255) / 256;   // 391
    k_mlp<<<nblk, 512, MLP_SMEM_BYTES>>>(feats, out);
}

// round 10
// speedup vs baseline: 1.1692x; 1.0448x over previous
#include <cuda_runtime.h>
#include <cuda_fp16.h>
#include <math.h>
#include <stdint.h>

#define DD 64
#define CC 256
#define RR 128
#define NPTS 100000
#define VV (DD*DD*DD)

// ---------------- scratch (static device globals; no allocations) ----------
__device__ int     g_idx  [VV];               // [x][y][z] -> point or -1
__device__ int     g_idx_t[VV];               // [z][x*64+y] -> point or -1
// z-passed grid, layout [z][cs][xy][8 half2]  (cs = channel slice of 16 ch)
__device__ __half2 g_h1[(size_t)VV * 128];
__device__ __half2 g_y [(size_t)NPTS * 128];  // gathered pooled features

#define SWS    264                 // sW1T [128 n][264] half
#define SW2S_H 136                 // sW2T [256 n][136] half
__device__ __align__(16) __half g_w1p[RR*SWS];     // prepacked W1^T, padded
__device__ __align__(16) __half g_w2p[CC*SW2S_H];  // prepacked W2^T, padded

#define NEGINF (-INFINITY)

// ---------------- fused init + weight prepack -------------------------------
__global__ void k_init_prepack(const float* __restrict__ W1,
                               const float* __restrict__ W2) {
    int i = blockIdx.x * blockDim.x + threadIdx.x;   // grid covers VV = 262144
    if (i < VV) { g_idx[i] = -1; g_idx_t[i] = -1; }
    if (i < CC*RR) {
        { int k = i >> 7, n = i & 127; g_w1p[n*SWS    + k] = __float2half(W1[i]); }
        { int k = i >> 8, n = i & 255; g_w2p[n*SW2S_H + k] = __float2half(W2[i]); }
    }
}

__global__ void k_scatter(const int* __restrict__ coords) {
    int i = blockIdx.x * blockDim.x + threadIdx.x;
    if (i < NPTS) {
        int ix = coords[3*i], iy = coords[3*i+1], iz = coords[3*i+2];
        g_idx  [(ix*DD + iy)*DD + iz] = i;
        g_idx_t[iz*4096 + ix*DD + iy] = i;
    }
}

// ---------------- helpers ---------------------------------------------------
#define SHIFT1(w, v) do { w[6]=w[5]; w[5]=w[4]; w[4]=w[3]; w[3]=w[2]; w[2]=w[1]; w[1]=w[0]; w[0]=(v); } while(0)
__device__ __forceinline__ __half2 max7h(const __half2* w) {
    return __hmax2(__hmax2(__hmax2(w[0],w[1]),__hmax2(w[2],w[3])),
                   __hmax2(__hmax2(w[4],w[5]),w[6]));
}

// ---------------- z-pass: distance-3 prefetch -------------------------------
// grid: 128 column-blocks (32 cols) x 16 channel slices = 2048 CTAs, 256 thr.
__global__ __launch_bounds__(256) void k_pool_z(const float* __restrict__ feats) {
    int cb = blockIdx.x >> 4;          // column block: columns cb*32 .. +31
    int cs = blockIdx.x & 15;          // channel slice (16 ch = 8 half2)
    int cl = threadIdx.x >> 3;         // 0..31 column within block
    int c  = threadIdx.x & 7;          // half2 within slice

    __shared__ int pid[32*DD];
    #pragma unroll
    for (int k = 0; k < 8; k++)
        pid[threadIdx.x + 256*k] = g_idx[cb*2048 + threadIdx.x + 256*k];
    __syncthreads();

    const __half2 NEG2 = __float2half2_rn(NEGINF);
    __half2 w[7];
    #pragma unroll
    for (int i = 0; i < 7; i++) w[i] = NEG2;

    const int xy = cb*32 + cl;
    const float* fbase = feats + cs*16 + c*2;
    const int* mypid = pid + cl*DD;

    // warm the pipeline: taps 0..2
    float2 fA = make_float2(NEGINF, NEGINF);
    float2 fB = make_float2(NEGINF, NEGINF);
    float2 fC = make_float2(NEGINF, NEGINF);
    { int p = mypid[0]; if (p >= 0) fA = *(const float2*)(fbase + (size_t)p*CC); }
    { int p = mypid[1]; if (p >= 0) fB = *(const float2*)(fbase + (size_t)p*CC); }
    { int p = mypid[2]; if (p >= 0) fC = *(const float2*)(fbase + (size_t)p*CC); }

    // tap loop: consume tap t, prefetch tap t+3
    #pragma unroll 4
    for (int t = 0; t < DD + 3; t++) {
        float2 cur = fA;
        fA = fB;
        fB = fC;
        fC = make_float2(NEGINF, NEGINF);
        int tn = t + 3;
        if (tn < DD) {
            int p = mypid[tn];
            if (p >= 0) fC = *(const float2*)(fbase + (size_t)p*CC);
        }
        SHIFT1(w, __floats2half2_rn(cur.x, cur.y));
        if (t >= 3) {
            int z = t - 3;
            g_h1[((size_t)(z*16 + cs)*4096 + xy)*8 + c] = max7h(w);
        }
    }
}

// ---------------- fused y-pass + x-pass + gather (512 threads) --------------
#define TXS 520                                    // words per x row
#define YX_SMEM_BYTES ((64*TXS + 4096) * 4)        // 149504

__global__ __launch_bounds__(512) void k_pool_yx() {
    extern __shared__ unsigned smw[];
    unsigned* sT  = smw;                 // tile, word = half2
    int*      spid = (int*)(smw + 64*TXS);

    int z  = blockIdx.x >> 4;
    int cs = blockIdx.x & 15;
    int tid = threadIdx.x;

    const uint4* src = (const uint4*)(g_h1 + (size_t)(z*16 + cs)*32768);
    #pragma unroll
    for (int k = 0; k < 16; k++) {
        int q = tid + 512*k;
        uint4 v = src[q];
        int w0 = q*4;
        int xy = w0 >> 3, c0 = w0 & 7;
        *(uint4*)&sT[(xy>>6)*TXS + (xy&63)*8 + c0] = v;
    }
    {
        const uint4* isrc = (const uint4*)(g_idx_t + z*4096);
        #pragma unroll
        for (int k = 0; k < 2; k++)
            *(uint4*)&spid[(tid + 512*k)*4] = isrc[tid + 512*k];
    }
    __syncthreads();

    const __half2 NEG2 = __float2half2_rn(NEGINF);

    {   // y-pass, in-place
        int x = tid >> 3, c = tid & 7;
        unsigned* col = sT + x*TXS + c;
        __half2 w[7];
        #pragma unroll
        for (int i = 0; i < 7; i++) w[i] = NEG2;
        #pragma unroll
        for (int yy = 0; yy < 3; yy++) { unsigned r = col[yy*8]; SHIFT1(w, *(__half2*)&r); }
        #pragma unroll 4
        for (int y = 0; y < DD; y++) {
            int yy = y + 3;
            __half2 v = NEG2;
            if (yy < DD) { unsigned r = col[yy*8]; v = *(__half2*)&r; }
            SHIFT1(w, v);
            __half2 o = max7h(w);
            col[y*8] = *(unsigned*)&o;
        }
    }
    __syncthreads();

    {   // x-pass + sparse gather
        int y = tid >> 3, c = tid & 7;
        unsigned* col = sT + y*8 + c;
        __half2 w[7];
        #pragma unroll
        for (int i = 0; i < 7; i++) w[i] = NEG2;
        #pragma unroll
        for (int xx = 0; xx < 3; xx++) { unsigned r = col[xx*TXS]; SHIFT1(w, *(__half2*)&r); }
        #pragma unroll 4
        for (int x = 0; x < DD; x++) {
            int xx = x + 3;
            __half2 v = NEG2;
            if (xx < DD) { unsigned r = col[xx*TXS]; v = *(__half2*)&r; }
            SHIFT1(w, v);
            int p = spid[x*64 + y];
            if (p >= 0) g_y[(size_t)p*128 + cs*8 + c] = max7h(w);
        }
    }
}

// ---------------- fused MLP (8Mx2N warps, ldmatrix A+B) ---------------------
// fp16 mma m16n8k16; 512 threads = 16 warps; 256 rows/CTA.

__device__ __forceinline__ uint32_t s2u(const void* p) {
    return (uint32_t)__cvta_generic_to_shared(p);
}
__device__ __forceinline__ void ldmA(uint32_t* a, const void* p) {
    asm volatile("ldmatrix.sync.aligned.m8n8.x4.shared.b16 {%0,%1,%2,%3}, [%4];"
        : "=r"(a[0]),"=r"(a[1]),"=r"(a[2]),"=r"(a[3]) : "r"(s2u(p)));
}
__device__ __forceinline__ void ldmB4(uint32_t* b, uint32_t saddr) {
    asm volatile("ldmatrix.sync.aligned.m8n8.x4.shared.b16 {%0,%1,%2,%3}, [%4];"
        : "=r"(b[0]),"=r"(b[1]),"=r"(b[2]),"=r"(b[3]) : "r"(saddr));
}
__device__ __forceinline__ void mma16(float* d, const uint32_t* a, const uint32_t* b,
                                      const float* c) {
    asm volatile("mma.sync.aligned.m16n8k16.row.col.f32.f16.f16.f32 "
        "{%0,%1,%2,%3}, {%4,%5,%6,%7}, {%8,%9}, {%10,%11,%12,%13};"
        : "=f"(d[0]),"=f"(d[1]),"=f"(d[2]),"=f"(d[3])
        : "r"(a[0]),"r"(a[1]),"r"(a[2]),"r"(a[3]),
          "r"(b[0]),"r"(b[1]),
          "f"(c[0]),"f"(c[1]),"f"(c[2]),"f"(c[3]));
}

#define SAS 264                     // sA [256 m][264] half (also sH region)
#define SHS_H 136                   // sH [256 m][136] half (inside sA region)
#define AW_HALFS (256*SAS)          // 67584 halfs = 135168 B
#define MLP_SMEM_BYTES (AW_HALFS*2 + 256*SW2S_H*2)   // 204800

__global__ __launch_bounds__(512, 1) void k_mlp(
    const float* __restrict__ feats, float* __restrict__ out) {
    extern __shared__ __half smh[];
    __half* sA  = smh;                       // phase A: A tile; phase B: sH
    __half* sW  = smh + AW_HALFS;            // phase A: W1T; phase B: W2T
    __half* sH  = smh;

    int tid = threadIdx.x;
    int lane = tid & 31, wid = tid >> 5;
    int group = lane >> 2, tg = lane & 3;
    int warpM = wid & 7, warpN = wid >> 3;   // 8 x 2
    int rowbase = warpM * 32;
    int colbase = warpN * 64;
    int m0 = blockIdx.x * 256;

    // ldmatrix-B per-lane tile addressing
    int bg = lane >> 3, br = lane & 7;
    int b_nt_off = (bg >> 1);                // 0/1 : which nt within the pair
    int b_k_off  = (bg & 1) * 8;             // 0/8 : k half

    // stage A tile (256 rows x 256 halfs) from g_y with uint4 loads
    {
        const __half* Yh = (const __half*)g_y;
        #pragma unroll
        for (int k = 0; k < 16; k++) {
            int u = tid + 512*k;             // uint4 index, 8192 total
            int row = u >> 5, cw = (u & 31)*8;
            int gr = m0 + row; if (gr >= NPTS) gr = NPTS - 1;
            uint4 v = *(const uint4*)(Yh + (size_t)gr*CC + cw);
            *(uint4*)&sA[row*SAS + cw] = v;
        }
    }
    // stage prepacked W1T: 4224 uint4
    {
        const uint4* wsrc = (const uint4*)g_w1p;
        uint4* wdst = (uint4*)sW;
        #pragma unroll
        for (int k = 0; k < 9; k++) {
            int u = tid + 512*k;
            if (u < (RR*SWS)/8) wdst[u] = wsrc[u];
        }
    }
    __syncthreads();

    // ---- GEMM1: H[256][128] = A @ W1 ----
    int lrow = lane & 15;
    int lk   = (lane >> 4) * 8;
    {
        uint32_t bp[4];
        #pragma unroll
        for (int j = 0; j < 4; j++)
            bp[j] = s2u(&sW[(colbase + (2*j + b_nt_off)*8 + br)*SWS + b_k_off]);

        float acc[2][8][4];
        #pragma unroll
        for (int mt = 0; mt < 2; mt++)
            #pragma unroll
            for (int nt = 0; nt < 8; nt++)
                #pragma unroll
                for (int q = 0; q < 4; q++) acc[mt][nt][q] = 0.f;

        for (int k0 = 0; k0 < CC; k0 += 16) {
            uint32_t a[2][4];
            #pragma unroll
            for (int mt = 0; mt < 2; mt++)
                ldmA(a[mt], &sA[(rowbase + mt*16 + lrow)*SAS + k0 + lk]);
            uint32_t b[8][2];
            #pragma unroll
            for (int j = 0; j < 4; j++) {
                uint32_t bb[4];
                ldmB4(bb, bp[j] + k0*2);
                b[2*j][0]   = bb[0]; b[2*j][1]   = bb[1];
                b[2*j+1][0] = bb[2]; b[2*j+1][1] = bb[3];
            }
            #pragma unroll
            for (int mt = 0; mt < 2; mt++)
                #pragma unroll
                for (int nt = 0; nt < 8; nt++)
                    mma16(acc[mt][nt], a[mt], b[nt], acc[mt][nt]);
        }
        __syncthreads();   // everyone done reading sA / sW

        // relu -> sH (fp16, reuses sA region)
        #pragma unroll
        for (int mt = 0; mt < 2; mt++)
            #pragma unroll
            for (int nt = 0; nt < 8; nt++) {
                int rl = rowbase + mt*16 + group;
                int cl = colbase + nt*8 + 2*tg;
                __half2 h0 = __floats2half2_rn(fmaxf(acc[mt][nt][0],0.f),
                                               fmaxf(acc[mt][nt][1],0.f));
                __half2 h1 = __floats2half2_rn(fmaxf(acc[mt][nt][2],0.f),
                                               fmaxf(acc[mt][nt][3],0.f));
                *(__half2*)&sH[rl*SHS_H + cl]     = h0;
                *(__half2*)&sH[(rl+8)*SHS_H + cl] = h1;
            }
    }
    // stage prepacked W2T: 4352 uint4
    {
        const uint4* wsrc = (const uint4*)g_w2p;
        uint4* wdst = (uint4*)sW;
        #pragma unroll
        for (int k = 0; k < 9; k++) {
            int u = tid + 512*k;
            if (u < (CC*SW2S_H)/8) wdst[u] = wsrc[u];
        }
    }
    __syncthreads();

    // ---- GEMM2: Z = H @ W2, two 64-col passes per warp ----
    for (int p = 0; p < 2; p++) {
        int cb = warpN*128 + p*64;
        uint32_t bp[4];
        #pragma unroll
        for (int j = 0; j < 4; j++)
            bp[j] = s2u(&sW[(cb + (2*j + b_nt_off)*8 + br)*SW2S_H + b_k_off]);

        float acc2[2][8][4];
        #pragma unroll
        for (int mt = 0; mt < 2; mt++)
            #pragma unroll
            for (int nt = 0; nt < 8; nt++)
                #pragma unroll
                for (int q = 0; q < 4; q++) acc2[mt][nt][q] = 0.f;

        for (int k0 = 0; k0 < RR; k0 += 16) {
            uint32_t a[2][4];
            #pragma unroll
            for (int mt = 0; mt < 2; mt++)
                ldmA(a[mt], &sH[(rowbase + mt*16 + lrow)*SHS_H + k0 + lk]);
            uint32_t b[8][2];
            #pragma unroll
            for (int j = 0; j < 4; j++) {
                uint32_t bb[4];
                ldmB4(bb, bp[j] + k0*2);
                b[2*j][0]   = bb[0]; b[2*j][1]   = bb[1];
                b[2*j+1][0] = bb[2]; b[2*j+1][1] = bb[3];
            }
            #pragma unroll
            for (int mt = 0; mt < 2; mt++)
                #pragma unroll
                for (int nt = 0; nt < 8; nt++)
                    mma16(acc2[mt][nt], a[mt], b[nt], acc2[mt][nt]);
        }

        // epilogue: sigmoid, multiply feats, store
        #pragma unroll
        for (int mt = 0; mt < 2; mt++)
            #pragma unroll
            for (int nt = 0; nt < 8; nt++) {
                int rl = rowbase + mt*16 + group;
                int cl = cb + nt*8 + 2*tg;
                int gi0 = m0 + rl, gi1 = gi0 + 8;
                if (gi0 < NPTS) {
                    float2 f = *(const float2*)(feats + (size_t)gi0*CC + cl);
                    float s0 = 1.f/(1.f + __expf(-acc2[mt][nt][0]));
                    float s1 = 1.f/(1.f + __expf(-acc2[mt][nt][1]));
                    float2 o; o.x = f.x*s0; o.y = f.y*s1;
                    *(float2*)(out + (size_t)gi0*CC + cl) = o;
                }
                if (gi1 < NPTS) {
                    float2 f = *(const float2*)(feats + (size_t)gi1*CC + cl);
                    float s2 = 1.f/(1.f + __expf(-acc2[mt][nt][2]));
                    float s3 = 1.f/(1.f + __expf(-acc2[mt][nt][3]));
                    float2 o; o.x = f.x*s2; o.y = f.y*s3;
                    *(float2*)(out + (size_t)gi1*CC + cl) = o;
                }
            }
    }
}

// ---------------- launch ----------------------------------------------------
extern "C" void kernel_launch(void* const* d_in, const int* in_sizes, int n_in,
                              void* d_out, int out_size) {
    const float* feats  = (const float*)d_in[0];
    const int*   coords = (const int*)d_in[1];
    const float* W1     = (const float*)d_in[2];
    const float* W2     = (const float*)d_in[3];
    float*       out    = (float*)d_out;

    k_init_prepack<<<(VV + 255)/256, 256>>>(W1, W2);
    k_scatter<<<(NPTS + 255)/256, 256>>>(coords);
    k_pool_z<<<2048, 256>>>(feats);

    cudaFuncSetAttribute(k_pool_yx, cudaFuncAttributeMaxDynamicSharedMemorySize,
                         YX_SMEM_BYTES);
    k_pool_yx<<<1024, 512, YX_SMEM_BYTES>>>();

    cudaFuncSetAttribute(k_mlp, cudaFuncAttributeMaxDynamicSharedMemorySize,
                         MLP_SMEM_BYTES);
    int nblk = (NPTS + 255) / 256;   // 391
    k_mlp<<<nblk, 512, MLP_SMEM_BYTES>>>(feats, out);
}

// round 11
// speedup vs baseline: 1.1698x; 1.0005x over previous
#include <cuda_runtime.h>
#include <cuda_fp16.h>
#include <math.h>
#include <stdint.h>

#define DD 64
#define CC 256
#define RR 128
#define NPTS 100000
#define VV (DD*DD*DD)

// ---------------- scratch (static device globals; no allocations) ----------
__device__ int     g_idx  [VV];               // [x][y][z] -> point or -1
__device__ int     g_idx_t[VV];               // [z][x*64+y] -> point or -1
// z-passed grid, layout [z][cs32][xy][4 half2]  (cs32 = 8-channel slice)
__device__ __half2 g_h1[(size_t)VV * 128];
__device__ __half2 g_y [(size_t)NPTS * 128];  // gathered pooled features

#define SWS    264                 // sW1T [128 n][264] half
#define SW2S_H 136                 // sW2T [256 n][136] half
__device__ __align__(16) __half g_w1p[RR*SWS];     // prepacked W1^T, padded
__device__ __align__(16) __half g_w2p[CC*SW2S_H];  // prepacked W2^T, padded

#define NEGINF (-INFINITY)

// ---------------- fused init + weight prepack -------------------------------
__global__ void k_init_prepack(const float* __restrict__ W1,
                               const float* __restrict__ W2) {
    int i = blockIdx.x * blockDim.x + threadIdx.x;   // grid covers VV = 262144
    if (i < VV) { g_idx[i] = -1; g_idx_t[i] = -1; }
    if (i < CC*RR) {
        { int k = i >> 7, n = i & 127; g_w1p[n*SWS    + k] = __float2half(W1[i]); }
        { int k = i >> 8, n = i & 255; g_w2p[n*SW2S_H + k] = __float2half(W2[i]); }
    }
}

__global__ void k_scatter(const int* __restrict__ coords) {
    int i = blockIdx.x * blockDim.x + threadIdx.x;
    if (i < NPTS) {
        int ix = coords[3*i], iy = coords[3*i+1], iz = coords[3*i+2];
        g_idx  [(ix*DD + iy)*DD + iz] = i;
        g_idx_t[iz*4096 + ix*DD + iy] = i;
    }
}

// ---------------- helpers ---------------------------------------------------
#define SHIFT1(w, v) do { w[6]=w[5]; w[5]=w[4]; w[4]=w[3]; w[3]=w[2]; w[2]=w[1]; w[1]=w[0]; w[0]=(v); } while(0)
__device__ __forceinline__ __half2 max7h(const __half2* w) {
    return __hmax2(__hmax2(__hmax2(w[0],w[1]),__hmax2(w[2],w[3])),
                   __hmax2(__hmax2(w[4],w[5]),w[6]));
}

// ---------------- z-pass: distance-3 prefetch, [z][cs32][xy][4] layout ------
// grid: 128 column-blocks (32 cols) x 16 channel slices = 2048 CTAs, 256 thr.
__global__ __launch_bounds__(256) void k_pool_z(const float* __restrict__ feats) {
    int cb = blockIdx.x >> 4;          // column block: columns cb*32 .. +31
    int cs = blockIdx.x & 15;          // 16-ch slice (8 half2)
    int cl = threadIdx.x >> 3;         // 0..31 column within block
    int c  = threadIdx.x & 7;          // half2 within 16-ch slice

    __shared__ int pid[32*DD];
    #pragma unroll
    for (int k = 0; k < 8; k++)
        pid[threadIdx.x + 256*k] = g_idx[cb*2048 + threadIdx.x + 256*k];
    __syncthreads();

    const __half2 NEG2 = __float2half2_rn(NEGINF);
    __half2 w[7];
    #pragma unroll
    for (int i = 0; i < 7; i++) w[i] = NEG2;

    const int xy  = cb*32 + cl;
    const int cs2 = cs*2 + (c >> 2);   // 8-channel slice index 0..31
    const int c2  = c & 3;             // half2 within 8-ch slice
    const float* fbase = feats + cs*16 + c*2;
    const int* mypid = pid + cl*DD;
    __half2* obase = g_h1 + ((size_t)cs2*4096 + xy)*4 + c2;   // + z*32*4096*4

    // warm the pipeline: taps 0..2
    float2 fA = make_float2(NEGINF, NEGINF);
    float2 fB = make_float2(NEGINF, NEGINF);
    float2 fC = make_float2(NEGINF, NEGINF);
    { int p = mypid[0]; if (p >= 0) fA = *(const float2*)(fbase + (size_t)p*CC); }
    { int p = mypid[1]; if (p >= 0) fB = *(const float2*)(fbase + (size_t)p*CC); }
    { int p = mypid[2]; if (p >= 0) fC = *(const float2*)(fbase + (size_t)p*CC); }

    // tap loop: consume tap t, prefetch tap t+3
    #pragma unroll 4
    for (int t = 0; t < DD + 3; t++) {
        float2 cur = fA;
        fA = fB;
        fB = fC;
        fC = make_float2(NEGINF, NEGINF);
        int tn = t + 3;
        if (tn < DD) {
            int p = mypid[tn];
            if (p >= 0) fC = *(const float2*)(fbase + (size_t)p*CC);
        }
        SHIFT1(w, __floats2half2_rn(cur.x, cur.y));
        if (t >= 3) {
            int z = t - 3;
            obase[(size_t)z * (32*4096*4)] = max7h(w);
        }
    }
}

// ---------------- fused y-pass + x-pass + gather (256 thr, 2 CTAs/SM) -------
// grid: 64 z-slices x 32 8-channel slices = 2048 CTAs.
#define TXS2 260                                   // words per x row (4/xy + pad)
#define YX_SMEM_BYTES ((64*TXS2 + 4096) * 4)       // 66560 + 16384 = 82944

__global__ __launch_bounds__(256) void k_pool_yx() {
    extern __shared__ unsigned smw[];
    unsigned* sT  = smw;                 // tile, word = half2
    int*      spid = (int*)(smw + 64*TXS2);

    int z  = blockIdx.x >> 5;
    int cs = blockIdx.x & 31;            // 8-channel slice
    int tid = threadIdx.x;

    // load slab (contiguous 65536 B): uint4 q = one xy's 4 half2
    const uint4* src = (const uint4*)(g_h1 + (size_t)(z*32 + cs)*16384);
    #pragma unroll
    for (int k = 0; k < 16; k++) {
        int q = tid + 256*k;             // xy index
        uint4 v = src[q];
        *(uint4*)&sT[(q>>6)*TXS2 + (q&63)*4] = v;
    }
    // load transposed idx for this z-slice
    {
        const uint4* isrc = (const uint4*)(g_idx_t + z*4096);
        #pragma unroll
        for (int k = 0; k < 4; k++)
            ((uint4*)spid)[tid + 256*k] = isrc[tid + 256*k];
    }
    __syncthreads();

    const __half2 NEG2 = __float2half2_rn(NEGINF);

    {   // y-pass, in-place. one column (x, c) per thread (256 columns)
        int x = tid >> 2, c = tid & 3;
        unsigned* col = sT + x*TXS2 + c;
        __half2 w[7];
        #pragma unroll
        for (int i = 0; i < 7; i++) w[i] = NEG2;
        #pragma unroll
        for (int yy = 0; yy < 3; yy++) { unsigned r = col[yy*4]; SHIFT1(w, *(__half2*)&r); }
        #pragma unroll 4
        for (int y = 0; y < DD; y++) {
            int yy = y + 3;
            __half2 v = NEG2;
            if (yy < DD) { unsigned r = col[yy*4]; v = *(__half2*)&r; }
            SHIFT1(w, v);
            __half2 o = max7h(w);
            col[y*4] = *(unsigned*)&o;
        }
    }
    __syncthreads();

    {   // x-pass + sparse gather. one column (y, c) per thread
        int y = tid >> 2, c = tid & 3;
        unsigned* col = sT + y*4 + c;
        __half2 w[7];
        #pragma unroll
        for (int i = 0; i < 7; i++) w[i] = NEG2;
        #pragma unroll
        for (int xx = 0; xx < 3; xx++) { unsigned r = col[xx*TXS2]; SHIFT1(w, *(__half2*)&r); }
        #pragma unroll 4
        for (int x = 0; x < DD; x++) {
            int xx = x + 3;
            __half2 v = NEG2;
            if (xx < DD) { unsigned r = col[xx*TXS2]; v = *(__half2*)&r; }
            SHIFT1(w, v);
            int p = spid[x*64 + y];
            if (p >= 0) g_y[(size_t)p*128 + cs*4 + c] = max7h(w);
        }
    }
}

// ---------------- fused MLP (8Mx2N warps, ldmatrix A+B) ---------------------
// fp16 mma m16n8k16; 512 threads = 16 warps; 256 rows/CTA.

__device__ __forceinline__ uint32_t s2u(const void* p) {
    return (uint32_t)__cvta_generic_to_shared(p);
}
__device__ __forceinline__ void ldmA(uint32_t* a, const void* p) {
    asm volatile("ldmatrix.sync.aligned.m8n8.x4.shared.b16 {%0,%1,%2,%3}, [%4];"
        : "=r"(a[0]),"=r"(a[1]),"=r"(a[2]),"=r"(a[3]) : "r"(s2u(p)));
}
__device__ __forceinline__ void ldmB4(uint32_t* b, uint32_t saddr) {
    asm volatile("ldmatrix.sync.aligned.m8n8.x4.shared.b16 {%0,%1,%2,%3}, [%4];"
        : "=r"(b[0]),"=r"(b[1]),"=r"(b[2]),"=r"(b[3]) : "r"(saddr));
}
__device__ __forceinline__ void mma16(float* d, const uint32_t* a, const uint32_t* b,
                                      const float* c) {
    asm volatile("mma.sync.aligned.m16n8k16.row.col.f32.f16.f16.f32 "
        "{%0,%1,%2,%3}, {%4,%5,%6,%7}, {%8,%9}, {%10,%11,%12,%13};"
        : "=f"(d[0]),"=f"(d[1]),"=f"(d[2]),"=f"(d[3])
        : "r"(a[0]),"r"(a[1]),"r"(a[2]),"r"(a[3]),
          "r"(b[0]),"r"(b[1]),
          "f"(c[0]),"f"(c[1]),"f"(c[2]),"f"(c[3]));
}

#define SAS 264                     // sA [256 m][264] half (also sH region)
#define SHS_H 136                   // sH [256 m][136] half (inside sA region)
#define AW_HALFS (256*SAS)          // 67584 halfs = 135168 B
#define MLP_SMEM_BYTES (AW_HALFS*2 + 256*SW2S_H*2)   // 204800

__global__ __launch_bounds__(512, 1) void k_mlp(
    const float* __restrict__ feats, float* __restrict__ out) {
    extern __shared__ __half smh[];
    __half* sA  = smh;                       // phase A: A tile; phase B: sH
    __half* sW  = smh + AW_HALFS;            // phase A: W1T; phase B: W2T
    __half* sH  = smh;

    int tid = threadIdx.x;
    int lane = tid & 31, wid = tid >> 5;
    int group = lane >> 2, tg = lane & 3;
    int warpM = wid & 7, warpN = wid >> 3;   // 8 x 2
    int rowbase = warpM * 32;
    int colbase = warpN * 64;
    int m0 = blockIdx.x * 256;

    // ldmatrix-B per-lane tile addressing
    int bg = lane >> 3, br = lane & 7;
    int b_nt_off = (bg >> 1);                // 0/1 : which nt within the pair
    int b_k_off  = (bg & 1) * 8;             // 0/8 : k half

    // stage A tile (256 rows x 256 halfs) from g_y with uint4 loads
    {
        const __half* Yh = (const __half*)g_y;
        #pragma unroll
        for (int k = 0; k < 16; k++) {
            int u = tid + 512*k;             // uint4 index, 8192 total
            int row = u >> 5, cw = (u & 31)*8;
            int gr = m0 + row; if (gr >= NPTS) gr = NPTS - 1;
            uint4 v = *(const uint4*)(Yh + (size_t)gr*CC + cw);
            *(uint4*)&sA[row*SAS + cw] = v;
        }
    }
    // stage prepacked W1T: 4224 uint4
    {
        const uint4* wsrc = (const uint4*)g_w1p;
        uint4* wdst = (uint4*)sW;
        #pragma unroll
        for (int k = 0; k < 9; k++) {
            int u = tid + 512*k;
            if (u < (RR*SWS)/8) wdst[u] = wsrc[u];
        }
    }
    __syncthreads();

    // ---- GEMM1: H[256][128] = A @ W1 ----
    int lrow = lane & 15;
    int lk   = (lane >> 4) * 8;
    {
        uint32_t bp[4];
        #pragma unroll
        for (int j = 0; j < 4; j++)
            bp[j] = s2u(&sW[(colbase + (2*j + b_nt_off)*8 + br)*SWS + b_k_off]);

        float acc[2][8][4];
        #pragma unroll
        for (int mt = 0; mt < 2; mt++)
            #pragma unroll
            for (int nt = 0; nt < 8; nt++)
                #pragma unroll
                for (int q = 0; q < 4; q++) acc[mt][nt][q] = 0.f;

        for (int k0 = 0; k0 < CC; k0 += 16) {
            uint32_t a[2][4];
            #pragma unroll
            for (int mt = 0; mt < 2; mt++)
                ldmA(a[mt], &sA[(rowbase + mt*16 + lrow)*SAS + k0 + lk]);
            uint32_t b[8][2];
            #pragma unroll
            for (int j = 0; j < 4; j++) {
                uint32_t bb[4];
                ldmB4(bb, bp[j] + k0*2);
                b[2*j][0]   = bb[0]; b[2*j][1]   = bb[1];
                b[2*j+1][0] = bb[2]; b[2*j+1][1] = bb[3];
            }
            #pragma unroll
            for (int mt = 0; mt < 2; mt++)
                #pragma unroll
                for (int nt = 0; nt < 8; nt++)
                    mma16(acc[mt][nt], a[mt], b[nt], acc[mt][nt]);
        }
        __syncthreads();   // everyone done reading sA / sW

        // relu -> sH (fp16, reuses sA region)
        #pragma unroll
        for (int mt = 0; mt < 2; mt++)
            #pragma unroll
            for (int nt = 0; nt < 8; nt++) {
                int rl = rowbase + mt*16 + group;
                int cl = colbase + nt*8 + 2*tg;
                __half2 h0 = __floats2half2_rn(fmaxf(acc[mt][nt][0],0.f),
                                               fmaxf(acc[mt][nt][1],0.f));
                __half2 h1 = __floats2half2_rn(fmaxf(acc[mt][nt][2],0.f),
                                               fmaxf(acc[mt][nt][3],0.f));
                *(__half2*)&sH[rl*SHS_H + cl]     = h0;
                *(__half2*)&sH[(rl+8)*SHS_H + cl] = h1;
            }
    }
    // stage prepacked W2T: 4352 uint4
    {
        const uint4* wsrc = (const uint4*)g_w2p;
        uint4* wdst = (uint4*)sW;
        #pragma unroll
        for (int k = 0; k < 9; k++) {
            int u = tid + 512*k;
            if (u < (CC*SW2S_H)/8) wdst[u] = wsrc[u];
        }
    }
    __syncthreads();

    // ---- GEMM2: Z = H @ W2, two 64-col passes per warp ----
    for (int p = 0; p < 2; p++) {
        int cb = warpN*128 + p*64;
        uint32_t bp[4];
        #pragma unroll
        for (int j = 0; j < 4; j++)
            bp[j] = s2u(&sW[(cb + (2*j + b_nt_off)*8 + br)*SW2S_H + b_k_off]);

        float acc2[2][8][4];
        #pragma unroll
        for (int mt = 0; mt < 2; mt++)
            #pragma unroll
            for (int nt = 0; nt < 8; nt++)
                #pragma unroll
                for (int q = 0; q < 4; q++) acc2[mt][nt][q] = 0.f;

        for (int k0 = 0; k0 < RR; k0 += 16) {
            uint32_t a[2][4];
            #pragma unroll
            for (int mt = 0; mt < 2; mt++)
                ldmA(a[mt], &sH[(rowbase + mt*16 + lrow)*SHS_H + k0 + lk]);
            uint32_t b[8][2];
            #pragma unroll
            for (int j = 0; j < 4; j++) {
                uint32_t bb[4];
                ldmB4(bb, bp[j] + k0*2);
                b[2*j][0]   = bb[0]; b[2*j][1]   = bb[1];
                b[2*j+1][0] = bb[2]; b[2*j+1][1] = bb[3];
            }
            #pragma unroll
            for (int mt = 0; mt < 2; mt++)
                #pragma unroll
                for (int nt = 0; nt < 8; nt++)
                    mma16(acc2[mt][nt], a[mt], b[nt], acc2[mt][nt]);
        }

        // epilogue: sigmoid, multiply feats, store
        #pragma unroll
        for (int mt = 0; mt < 2; mt++)
            #pragma unroll
            for (int nt = 0; nt < 8; nt++) {
                int rl = rowbase + mt*16 + group;
                int cl = cb + nt*8 + 2*tg;
                int gi0 = m0 + rl, gi1 = gi0 + 8;
                if (gi0 < NPTS) {
                    float2 f = *(const float2*)(feats + (size_t)gi0*CC + cl);
                    float s0 = 1.f/(1.f + __expf(-acc2[mt][nt][0]));
                    float s1 = 1.f/(1.f + __expf(-acc2[mt][nt][1]));
                    float2 o; o.x = f.x*s0; o.y = f.y*s1;
                    *(float2*)(out + (size_t)gi0*CC + cl) = o;
                }
                if (gi1 < NPTS) {
                    float2 f = *(const float2*)(feats + (size_t)gi1*CC + cl);
                    float s2 = 1.f/(1.f + __expf(-acc2[mt][nt][2]));
                    float s3 = 1.f/(1.f + __expf(-acc2[mt][nt][3]));
                    float2 o; o.x = f.x*s2; o.y = f.y*s3;
                    *(float2*)(out + (size_t)gi1*CC + cl) = o;
                }
            }
    }
}

// ---------------- launch ----------------------------------------------------
extern "C" void kernel_launch(void* const* d_in, const int* in_sizes, int n_in,
                              void* d_out, int out_size) {
    const float* feats  = (const float*)d_in[0];
    const int*   coords = (const int*)d_in[1];
    const float* W1     = (const float*)d_in[2];
    const float* W2     = (const float*)d_in[3];
    float*       out    = (float*)d_out;

    k_init_prepack<<<(VV + 255)/256, 256>>>(W1, W2);
    k_scatter<<<(NPTS + 255)/256, 256>>>(coords);
    k_pool_z<<<2048, 256>>>(feats);

    cudaFuncSetAttribute(k_pool_yx, cudaFuncAttributeMaxDynamicSharedMemorySize,
                         YX_SMEM_BYTES);
    k_pool_yx<<<2048, 256, YX_SMEM_BYTES>>>();

    cudaFuncSetAttribute(k_mlp, cudaFuncAttributeMaxDynamicSharedMemorySize,
                         MLP_SMEM_BYTES);
    int nblk = (NPTS + 255) / 256;   // 391
    k_mlp<<<nblk, 512, MLP_SMEM_BYTES>>>(feats, out);
}

// round 12
// speedup vs baseline: 1.1912x; 1.0183x over previous
#include <cuda_runtime.h>
#include <cuda_fp16.h>
#include <math.h>
#include <stdint.h>

#define DD 64
#define CC 256
#define RR 128
#define NPTS 100000
#define VV (DD*DD*DD)

// ---------------- scratch (static device globals; no allocations) ----------
__device__ int     g_idx  [VV];               // [x][y][z] -> point or -1
__device__ int     g_idx_t[VV];               // [z][x*64+y] -> point or -1
// z-passed grid, layout [z][cs32][xy][4 half2]  (cs32 = 8-channel slice)
__device__ __half2 g_h1[(size_t)VV * 128];
__device__ __half2 g_y [(size_t)NPTS * 128];  // gathered pooled features

#define SWS    264                 // sW1T [128 n][264] half
#define SW2S_H 136                 // sW2T [256 n][136] half
__device__ __align__(16) __half g_w1p[RR*SWS];     // prepacked W1^T, padded
__device__ __align__(16) __half g_w2p[CC*SW2S_H];  // prepacked W2^T, padded

#define NEGINF (-INFINITY)

// ---------------- fused init + weight prepack -------------------------------
__global__ void k_init_prepack(const float* __restrict__ W1,
                               const float* __restrict__ W2) {
    int i = blockIdx.x * blockDim.x + threadIdx.x;   // grid covers VV = 262144
    if (i < VV) { g_idx[i] = -1; g_idx_t[i] = -1; }
    if (i < CC*RR) {
        { int k = i >> 7, n = i & 127; g_w1p[n*SWS    + k] = __float2half(W1[i]); }
        { int k = i >> 8, n = i & 255; g_w2p[n*SW2S_H + k] = __float2half(W2[i]); }
    }
}

__global__ void k_scatter(const int* __restrict__ coords) {
    int i = blockIdx.x * blockDim.x + threadIdx.x;
    if (i < NPTS) {
        int ix = coords[3*i], iy = coords[3*i+1], iz = coords[3*i+2];
        g_idx  [(ix*DD + iy)*DD + iz] = i;
        g_idx_t[iz*4096 + ix*DD + iy] = i;
    }
}

// ---------------- helpers ---------------------------------------------------
#define SHIFT1(w, v) do { w[6]=w[5]; w[5]=w[4]; w[4]=w[3]; w[3]=w[2]; w[2]=w[1]; w[1]=w[0]; w[0]=(v); } while(0)
__device__ __forceinline__ __half2 max7h(const __half2* w) {
    return __hmax2(__hmax2(__hmax2(w[0],w[1]),__hmax2(w[2],w[3])),
                   __hmax2(__hmax2(w[4],w[5]),w[6]));
}

// ---------------- z-pass: distance-3 prefetch, [z][cs32][xy][4] layout ------
// grid: 128 column-blocks (32 cols) x 16 channel slices = 2048 CTAs, 256 thr.
__global__ __launch_bounds__(256) void k_pool_z(const float* __restrict__ feats) {
    int cb = blockIdx.x >> 4;          // column block: columns cb*32 .. +31
    int cs = blockIdx.x & 15;          // 16-ch slice (8 half2)
    int cl = threadIdx.x >> 3;         // 0..31 column within block
    int c  = threadIdx.x & 7;          // half2 within 16-ch slice

    __shared__ int pid[32*DD];
    #pragma unroll
    for (int k = 0; k < 8; k++)
        pid[threadIdx.x + 256*k] = g_idx[cb*2048 + threadIdx.x + 256*k];
    __syncthreads();

    const __half2 NEG2 = __float2half2_rn(NEGINF);
    __half2 w[7];
    #pragma unroll
    for (int i = 0; i < 7; i++) w[i] = NEG2;

    const int xy  = cb*32 + cl;
    const int cs2 = cs*2 + (c >> 2);   // 8-channel slice index 0..31
    const int c2  = c & 3;             // half2 within 8-ch slice
    const float* fbase = feats + cs*16 + c*2;
    const int* mypid = pid + cl*DD;
    __half2* obase = g_h1 + ((size_t)cs2*4096 + xy)*4 + c2;   // + z*32*4096*4

    // warm the pipeline: taps 0..2
    float2 fA = make_float2(NEGINF, NEGINF);
    float2 fB = make_float2(NEGINF, NEGINF);
    float2 fC = make_float2(NEGINF, NEGINF);
    { int p = mypid[0]; if (p >= 0) fA = *(const float2*)(fbase + (size_t)p*CC); }
    { int p = mypid[1]; if (p >= 0) fB = *(const float2*)(fbase + (size_t)p*CC); }
    { int p = mypid[2]; if (p >= 0) fC = *(const float2*)(fbase + (size_t)p*CC); }

    // tap loop: consume tap t, prefetch tap t+3
    #pragma unroll 4
    for (int t = 0; t < DD + 3; t++) {
        float2 cur = fA;
        fA = fB;
        fB = fC;
        fC = make_float2(NEGINF, NEGINF);
        int tn = t + 3;
        if (tn < DD) {
            int p = mypid[tn];
            if (p >= 0) fC = *(const float2*)(fbase + (size_t)p*CC);
        }
        SHIFT1(w, __floats2half2_rn(cur.x, cur.y));
        if (t >= 3) {
            int z = t - 3;
            obase[(size_t)z * (32*4096*4)] = max7h(w);
        }
    }
}

// ---------------- fused y-pass + x-pass + gather (256 thr, 2 CTAs/SM) -------
// grid: 64 z-slices x 32 8-channel slices = 2048 CTAs. FULL UNROLL passes.
#define TXS2 260                                   // words per x row (4/xy + pad)
#define YX_SMEM_BYTES ((64*TXS2 + 4096) * 4)       // 66560 + 16384 = 82944

__global__ __launch_bounds__(256) void k_pool_yx() {
    extern __shared__ unsigned smw[];
    unsigned* sT  = smw;                 // tile, word = half2
    int*      spid = (int*)(smw + 64*TXS2);

    int z  = blockIdx.x >> 5;
    int cs = blockIdx.x & 31;            // 8-channel slice
    int tid = threadIdx.x;

    // load slab (contiguous 65536 B): uint4 q = one xy's 4 half2
    const uint4* src = (const uint4*)(g_h1 + (size_t)(z*32 + cs)*16384);
    #pragma unroll
    for (int k = 0; k < 16; k++) {
        int q = tid + 256*k;             // xy index
        uint4 v = src[q];
        *(uint4*)&sT[(q>>6)*TXS2 + (q&63)*4] = v;
    }
    // load transposed idx for this z-slice
    {
        const uint4* isrc = (const uint4*)(g_idx_t + z*4096);
        #pragma unroll
        for (int k = 0; k < 4; k++)
            ((uint4*)spid)[tid + 256*k] = isrc[tid + 256*k];
    }
    __syncthreads();

    const __half2 NEG2 = __float2half2_rn(NEGINF);

    {   // y-pass, in-place, FULLY UNROLLED. one column (x, c) per thread.
        int x = tid >> 2, c = tid & 3;
        unsigned* col = sT + x*TXS2 + c;
        __half2 w[7];
        #pragma unroll
        for (int i = 0; i < 7; i++) w[i] = NEG2;
        #pragma unroll
        for (int t = 0; t < DD + 3; t++) {
            __half2 v = NEG2;
            if (t < DD) { unsigned r = col[t*4]; v = *(__half2*)&r; }
            SHIFT1(w, v);
            if (t >= 3) {
                __half2 o = max7h(w);
                col[(t-3)*4] = *(unsigned*)&o;
            }
        }
    }
    __syncthreads();

    {   // x-pass + sparse gather, FULLY UNROLLED. one column (y, c) per thread.
        int y = tid >> 2, c = tid & 3;
        unsigned* col = sT + y*4 + c;
        const int* prow = spid + y;      // pid[x*64 + y]
        __half2 w[7];
        #pragma unroll
        for (int i = 0; i < 7; i++) w[i] = NEG2;
        #pragma unroll
        for (int t = 0; t < DD + 3; t++) {
            __half2 v = NEG2;
            if (t < DD) { unsigned r = col[t*TXS2]; v = *(__half2*)&r; }
            SHIFT1(w, v);
            if (t >= 3) {
                int p = prow[(t-3)*64];
                if (p >= 0) g_y[(size_t)p*128 + cs*4 + c] = max7h(w);
            }
        }
    }
}

// ---------------- fused MLP (8Mx2N warps, ldmatrix A+B) ---------------------
// fp16 mma m16n8k16; 512 threads = 16 warps; 256 rows/CTA.

__device__ __forceinline__ uint32_t s2u(const void* p) {
    return (uint32_t)__cvta_generic_to_shared(p);
}
__device__ __forceinline__ void ldmA(uint32_t* a, const void* p) {
    asm volatile("ldmatrix.sync.aligned.m8n8.x4.shared.b16 {%0,%1,%2,%3}, [%4];"
        : "=r"(a[0]),"=r"(a[1]),"=r"(a[2]),"=r"(a[3]) : "r"(s2u(p)));
}
__device__ __forceinline__ void ldmB4(uint32_t* b, uint32_t saddr) {
    asm volatile("ldmatrix.sync.aligned.m8n8.x4.shared.b16 {%0,%1,%2,%3}, [%4];"
        : "=r"(b[0]),"=r"(b[1]),"=r"(b[2]),"=r"(b[3]) : "r"(saddr));
}
__device__ __forceinline__ void mma16(float* d, const uint32_t* a, const uint32_t* b,
                                      const float* c) {
    asm volatile("mma.sync.aligned.m16n8k16.row.col.f32.f16.f16.f32 "
        "{%0,%1,%2,%3}, {%4,%5,%6,%7}, {%8,%9}, {%10,%11,%12,%13};"
        : "=f"(d[0]),"=f"(d[1]),"=f"(d[2]),"=f"(d[3])
        : "r"(a[0]),"r"(a[1]),"r"(a[2]),"r"(a[3]),
          "r"(b[0]),"r"(b[1]),
          "f"(c[0]),"f"(c[1]),"f"(c[2]),"f"(c[3]));
}

#define SAS 264                     // sA [256 m][264] half (also sH region)
#define SHS_H 136                   // sH [256 m][136] half (inside sA region)
#define AW_HALFS (256*SAS)          // 67584 halfs = 135168 B
#define MLP_SMEM_BYTES (AW_HALFS*2 + 256*SW2S_H*2)   // 204800

__global__ __launch_bounds__(512, 1) void k_mlp(
    const float* __restrict__ feats, float* __restrict__ out) {
    extern __shared__ __half smh[];
    __half* sA  = smh;                       // phase A: A tile; phase B: sH
    __half* sW  = smh + AW_HALFS;            // phase A: W1T; phase B: W2T
    __half* sH  = smh;

    int tid = threadIdx.x;
    int lane = tid & 31, wid = tid >> 5;
    int group = lane >> 2, tg = lane & 3;
    int warpM = wid & 7, warpN = wid >> 3;   // 8 x 2
    int rowbase = warpM * 32;
    int colbase = warpN * 64;
    int m0 = blockIdx.x * 256;

    // ldmatrix-B per-lane tile addressing
    int bg = lane >> 3, br = lane & 7;
    int b_nt_off = (bg >> 1);                // 0/1 : which nt within the pair
    int b_k_off  = (bg & 1) * 8;             // 0/8 : k half

    // stage A tile (256 rows x 256 halfs) from g_y with uint4 loads
    {
        const __half* Yh = (const __half*)g_y;
        #pragma unroll
        for (int k = 0; k < 16; k++) {
            int u = tid + 512*k;             // uint4 index, 8192 total
            int row = u >> 5, cw = (u & 31)*8;
            int gr = m0 + row; if (gr >= NPTS) gr = NPTS - 1;
            uint4 v = *(const uint4*)(Yh + (size_t)gr*CC + cw);
            *(uint4*)&sA[row*SAS + cw] = v;
        }
    }
    // stage prepacked W1T: 4224 uint4
    {
        const uint4* wsrc = (const uint4*)g_w1p;
        uint4* wdst = (uint4*)sW;
        #pragma unroll
        for (int k = 0; k < 9; k++) {
            int u = tid + 512*k;
            if (u < (RR*SWS)/8) wdst[u] = wsrc[u];
        }
    }
    __syncthreads();

    // ---- GEMM1: H[256][128] = A @ W1 ----
    int lrow = lane & 15;
    int lk   = (lane >> 4) * 8;
    {
        uint32_t bp[4];
        #pragma unroll
        for (int j = 0; j < 4; j++)
            bp[j] = s2u(&sW[(colbase + (2*j + b_nt_off)*8 + br)*SWS + b_k_off]);

        float acc[2][8][4];
        #pragma unroll
        for (int mt = 0; mt < 2; mt++)
            #pragma unroll
            for (int nt = 0; nt < 8; nt++)
                #pragma unroll
                for (int q = 0; q < 4; q++) acc[mt][nt][q] = 0.f;

        for (int k0 = 0; k0 < CC; k0 += 16) {
            uint32_t a[2][4];
            #pragma unroll
            for (int mt = 0; mt < 2; mt++)
                ldmA(a[mt], &sA[(rowbase + mt*16 + lrow)*SAS + k0 + lk]);
            uint32_t b[8][2];
            #pragma unroll
            for (int j = 0; j < 4; j++) {
                uint32_t bb[4];
                ldmB4(bb, bp[j] + k0*2);
                b[2*j][0]   = bb[0]; b[2*j][1]   = bb[1];
                b[2*j+1][0] = bb[2]; b[2*j+1][1] = bb[3];
            }
            #pragma unroll
            for (int mt = 0; mt < 2; mt++)
                #pragma unroll
                for (int nt = 0; nt < 8; nt++)
                    mma16(acc[mt][nt], a[mt], b[nt], acc[mt][nt]);
        }
        __syncthreads();   // everyone done reading sA / sW

        // relu -> sH (fp16, reuses sA region)
        #pragma unroll
        for (int mt = 0; mt < 2; mt++)
            #pragma unroll
            for (int nt = 0; nt < 8; nt++) {
                int rl = rowbase + mt*16 + group;
                int cl = colbase + nt*8 + 2*tg;
                __half2 h0 = __floats2half2_rn(fmaxf(acc[mt][nt][0],0.f),
                                               fmaxf(acc[mt][nt][1],0.f));
                __half2 h1 = __floats2half2_rn(fmaxf(acc[mt][nt][2],0.f),
                                               fmaxf(acc[mt][nt][3],0.f));
                *(__half2*)&sH[rl*SHS_H + cl]     = h0;
                *(__half2*)&sH[(rl+8)*SHS_H + cl] = h1;
            }
    }
    // stage prepacked W2T: 4352 uint4
    {
        const uint4* wsrc = (const uint4*)g_w2p;
        uint4* wdst = (uint4*)sW;
        #pragma unroll
        for (int k = 0; k < 9; k++) {
            int u = tid + 512*k;
            if (u < (CC*SW2S_H)/8) wdst[u] = wsrc[u];
        }
    }
    __syncthreads();

    // ---- GEMM2: Z = H @ W2, two 64-col passes per warp ----
    for (int p = 0; p < 2; p++) {
        int cb = warpN*128 + p*64;
        uint32_t bp[4];
        #pragma unroll
        for (int j = 0; j < 4; j++)
            bp[j] = s2u(&sW[(cb + (2*j + b_nt_off)*8 + br)*SW2S_H + b_k_off]);

        float acc2[2][8][4];
        #pragma unroll
        for (int mt = 0; mt < 2; mt++)
            #pragma unroll
            for (int nt = 0; nt < 8; nt++)
                #pragma unroll
                for (int q = 0; q < 4; q++) acc2[mt][nt][q] = 0.f;

        for (int k0 = 0; k0 < RR; k0 += 16) {
            uint32_t a[2][4];
            #pragma unroll
            for (int mt = 0; mt < 2; mt++)
                ldmA(a[mt], &sH[(rowbase + mt*16 + lrow)*SHS_H + k0 + lk]);
            uint32_t b[8][2];
            #pragma unroll
            for (int j = 0; j < 4; j++) {
                uint32_t bb[4];
                ldmB4(bb, bp[j] + k0*2);
                b[2*j][0]   = bb[0]; b[2*j][1]   = bb[1];
                b[2*j+1][0] = bb[2]; b[2*j+1][1] = bb[3];
            }
            #pragma unroll
            for (int mt = 0; mt < 2; mt++)
                #pragma unroll
                for (int nt = 0; nt < 8; nt++)
                    mma16(acc2[mt][nt], a[mt], b[nt], acc2[mt][nt]);
        }

        // epilogue: sigmoid, multiply feats, store
        #pragma unroll
        for (int mt = 0; mt < 2; mt++)
            #pragma unroll
            for (int nt = 0; nt < 8; nt++) {
                int rl = rowbase + mt*16 + group;
                int cl = cb + nt*8 + 2*tg;
                int gi0 = m0 + rl, gi1 = gi0 + 8;
                if (gi0 < NPTS) {
                    float2 f = *(const float2*)(feats + (size_t)gi0*CC + cl);
                    float s0 = 1.f/(1.f + __expf(-acc2[mt][nt][0]));
                    float s1 = 1.f/(1.f + __expf(-acc2[mt][nt][1]));
                    float2 o; o.x = f.x*s0; o.y = f.y*s1;
                    *(float2*)(out + (size_t)gi0*CC + cl) = o;
                }
                if (gi1 < NPTS) {
                    float2 f = *(const float2*)(feats + (size_t)gi1*CC + cl);
                    float s2 = 1.f/(1.f + __expf(-acc2[mt][nt][2]));
                    float s3 = 1.f/(1.f + __expf(-acc2[mt][nt][3]));
                    float2 o; o.x = f.x*s2; o.y = f.y*s3;
                    *(float2*)(out + (size_t)gi1*CC + cl) = o;
                }
            }
    }
}

// ---------------- launch ----------------------------------------------------
extern "C" void kernel_launch(void* const* d_in, const int* in_sizes, int n_in,
                              void* d_out, int out_size) {
    const float* feats  = (const float*)d_in[0];
    const int*   coords = (const int*)d_in[1];
    const float* W1     = (const float*)d_in[2];
    const float* W2     = (const float*)d_in[3];
    float*       out    = (float*)d_out;

    k_init_prepack<<<(VV + 255)/256, 256>>>(W1, W2);
    k_scatter<<<(NPTS + 255)/256, 256>>>(coords);
    k_pool_z<<<2048, 256>>>(feats);

    cudaFuncSetAttribute(k_pool_yx, cudaFuncAttributeMaxDynamicSharedMemorySize,
                         YX_SMEM_BYTES);
    k_pool_yx<<<2048, 256, YX_SMEM_BYTES>>>();

    cudaFuncSetAttribute(k_mlp, cudaFuncAttributeMaxDynamicSharedMemorySize,
                         MLP_SMEM_BYTES);
    int nblk = (NPTS + 255) / 256;   // 391
    k_mlp<<<nblk, 512, MLP_SMEM_BYTES>>>(feats, out);
}

// round 13
// speedup vs baseline: 1.2690x; 1.0653x over previous
#include <cuda_runtime.h>
#include <cuda_fp16.h>
#include <math.h>
#include <stdint.h>

#define DD 64
#define CC 256
#define RR 128
#define NPTS 100000
#define VV (DD*DD*DD)

// ---------------- scratch (static device globals; no allocations) ----------
__device__ int     g_idx  [VV];               // [x][y][z] -> point or -1
__device__ int     g_idx_t[VV];               // [z][x*64+y] -> point or -1
// z-passed grid, layout [z][cs32][xy][4 half2]  (cs32 = 8-channel slice)
__device__ __half2 g_h1[(size_t)VV * 128];
__device__ __half2 g_y [(size_t)NPTS * 128];  // gathered pooled features

#define SWS    264                 // sW1T [128 n][264] half
#define SW2S_H 136                 // sW2T [256 n][136] half
__device__ __align__(16) __half g_w1p[RR*SWS];     // prepacked W1^T, padded
__device__ __align__(16) __half g_w2p[CC*SW2S_H];  // prepacked W2^T, padded

#define NEGINF (-INFINITY)

// ---------------- fused init + weight prepack -------------------------------
__global__ void k_init_prepack(const float* __restrict__ W1,
                               const float* __restrict__ W2) {
    int i = blockIdx.x * blockDim.x + threadIdx.x;   // grid covers VV = 262144
    if (i < VV) { g_idx[i] = -1; g_idx_t[i] = -1; }
    if (i < CC*RR) {
        { int k = i >> 7, n = i & 127; g_w1p[n*SWS    + k] = __float2half(W1[i]); }
        { int k = i >> 8, n = i & 255; g_w2p[n*SW2S_H + k] = __float2half(W2[i]); }
    }
}

__global__ void k_scatter(const int* __restrict__ coords) {
    int i = blockIdx.x * blockDim.x + threadIdx.x;
    if (i < NPTS) {
        int ix = coords[3*i], iy = coords[3*i+1], iz = coords[3*i+2];
        g_idx  [(ix*DD + iy)*DD + iz] = i;
        g_idx_t[iz*4096 + ix*DD + iy] = i;
    }
}

// ---------------- helpers ---------------------------------------------------
#define SHIFT1(w, v) do { w[6]=w[5]; w[5]=w[4]; w[4]=w[3]; w[3]=w[2]; w[2]=w[1]; w[1]=w[0]; w[0]=(v); } while(0)
__device__ __forceinline__ __half2 max7h(const __half2* w) {
    return __hmax2(__hmax2(__hmax2(w[0],w[1]),__hmax2(w[2],w[3])),
                   __hmax2(__hmax2(w[4],w[5]),w[6]));
}

// ---------------- z-pass: distance-3 prefetch, [z][cs32][xy][4] layout ------
// grid: 128 column-blocks (32 cols) x 16 channel slices = 2048 CTAs, 256 thr.
__global__ __launch_bounds__(256) void k_pool_z(const float* __restrict__ feats) {
    int cb = blockIdx.x >> 4;          // column block: columns cb*32 .. +31
    int cs = blockIdx.x & 15;          // 16-ch slice (8 half2)
    int cl = threadIdx.x >> 3;         // 0..31 column within block
    int c  = threadIdx.x & 7;          // half2 within 16-ch slice

    __shared__ int pid[32*DD];
    #pragma unroll
    for (int k = 0; k < 8; k++)
        pid[threadIdx.x + 256*k] = g_idx[cb*2048 + threadIdx.x + 256*k];
    __syncthreads();

    const __half2 NEG2 = __float2half2_rn(NEGINF);
    __half2 w[7];
    #pragma unroll
    for (int i = 0; i < 7; i++) w[i] = NEG2;

    const int xy  = cb*32 + cl;
    const int cs2 = cs*2 + (c >> 2);   // 8-channel slice index 0..31
    const int c2  = c & 3;             // half2 within 8-ch slice
    const float* fbase = feats + cs*16 + c*2;
    const int* mypid = pid + cl*DD;
    __half2* obase = g_h1 + ((size_t)cs2*4096 + xy)*4 + c2;   // + z*32*4096*4

    // warm the pipeline: taps 0..2
    float2 fA = make_float2(NEGINF, NEGINF);
    float2 fB = make_float2(NEGINF, NEGINF);
    float2 fC = make_float2(NEGINF, NEGINF);
    { int p = mypid[0]; if (p >= 0) fA = *(const float2*)(fbase + (size_t)p*CC); }
    { int p = mypid[1]; if (p >= 0) fB = *(const float2*)(fbase + (size_t)p*CC); }
    { int p = mypid[2]; if (p >= 0) fC = *(const float2*)(fbase + (size_t)p*CC); }

    // tap loop: consume tap t, prefetch tap t+3
    #pragma unroll 4
    for (int t = 0; t < DD + 3; t++) {
        float2 cur = fA;
        fA = fB;
        fB = fC;
        fC = make_float2(NEGINF, NEGINF);
        int tn = t + 3;
        if (tn < DD) {
            int p = mypid[tn];
            if (p >= 0) fC = *(const float2*)(fbase + (size_t)p*CC);
        }
        SHIFT1(w, __floats2half2_rn(cur.x, cur.y));
        if (t >= 3) {
            int z = t - 3;
            obase[(size_t)z * (32*4096*4)] = max7h(w);
        }
    }
}

// ---------------- fused y-pass + x-pass + gather ----------------------------
// 512 threads, 2 CTAs/SM. Each column is split across two threads (output
// halves). y-pass is in-place: 3 boundary taps preloaded to regs pre-barrier.
#define TXS2 260                                   // words per x row (4/xy + pad)
#define YX_SMEM_BYTES ((64*TXS2 + 4096) * 4)       // 66560 + 16384 = 82944

template<int Y0>
__device__ __forceinline__ void ypass_half(unsigned* col,
                                           unsigned e0, unsigned e1, unsigned e2) {
    const __half2 NEG2 = __float2half2_rn(NEGINF);
    constexpr int F0 = (Y0 == 0) ? 32 : 29;        // foreign taps (other half writes)
    __half2 w[7];
    #pragma unroll
    for (int i = 0; i < 7; i++) w[i] = NEG2;
    #pragma unroll
    for (int i = 0; i < 38; i++) {
        int t = Y0 - 3 + i;                        // compile-time
        __half2 v = NEG2;
        if (t >= 0 && t < DD) {
            unsigned r;
            if      (t == F0)     r = e0;
            else if (t == F0 + 1) r = e1;
            else if (t == F0 + 2) r = e2;
            else                  r = col[t*4];
            v = *(__half2*)&r;
        }
        SHIFT1(w, v);
        int y = t - 3;
        if (y >= Y0 && y < Y0 + 32) {
            __half2 o = max7h(w);
            col[y*4] = *(unsigned*)&o;
        }
    }
}

template<int X0>
__device__ __forceinline__ void xpass_half(const unsigned* col, const int* prow,
                                           int cs, int c) {
    const __half2 NEG2 = __float2half2_rn(NEGINF);
    __half2 w[7];
    #pragma unroll
    for (int i = 0; i < 7; i++) w[i] = NEG2;
    #pragma unroll
    for (int i = 0; i < 38; i++) {
        int t = X0 - 3 + i;                        // compile-time
        __half2 v = NEG2;
        if (t >= 0 && t < DD) { unsigned r = col[t*TXS2]; v = *(__half2*)&r; }
        SHIFT1(w, v);
        int x = t - 3;
        if (x >= X0 && x < X0 + 32) {
            int p = prow[x*64];
            if (p >= 0) g_y[(size_t)p*128 + cs*4 + c] = max7h(w);
        }
    }
}

__global__ __launch_bounds__(512) void k_pool_yx() {
    extern __shared__ unsigned smw[];
    unsigned* sT  = smw;                 // tile, word = half2
    int*      spid = (int*)(smw + 64*TXS2);

    int z  = blockIdx.x >> 5;
    int cs = blockIdx.x & 31;            // 8-channel slice
    int tid = threadIdx.x;
    int half = tid >> 8;                 // 0: lower output range, 1: upper
    int sub  = tid & 255;

    // load slab (contiguous 65536 B): uint4 q = one xy's 4 half2
    const uint4* src = (const uint4*)(g_h1 + (size_t)(z*32 + cs)*16384);
    #pragma unroll
    for (int k = 0; k < 8; k++) {
        int q = tid + 512*k;             // xy index
        uint4 v = src[q];
        *(uint4*)&sT[(q>>6)*TXS2 + (q&63)*4] = v;
    }
    // load transposed idx for this z-slice
    {
        const uint4* isrc = (const uint4*)(g_idx_t + z*4096);
        #pragma unroll
        for (int k = 0; k < 2; k++)
            ((uint4*)spid)[tid + 512*k] = isrc[tid + 512*k];
    }
    __syncthreads();

    // ---- y-pass, in-place, split by output half ----
    {
        int x = sub >> 2, c = sub & 3;
        unsigned* col = sT + x*TXS2 + c;
        // preload foreign taps (rows the other half will overwrite)
        int F0 = (half == 0) ? 32 : 29;
        unsigned e0 = col[F0*4], e1 = col[(F0+1)*4], e2 = col[(F0+2)*4];
        __syncthreads();                 // preloads complete before any writes
        if (half == 0) ypass_half<0 >(col, e0, e1, e2);
        else           ypass_half<32>(col, e0, e1, e2);
    }
    __syncthreads();

    // ---- x-pass + sparse gather (writes to global only; no hazard) ----
    {
        int y = sub >> 2, c = sub & 3;
        const unsigned* col = sT + y*4 + c;
        const int* prow = spid + y;      // pid[x*64 + y]
        if (half == 0) xpass_half<0 >(col, prow, cs, c);
        else           xpass_half<32>(col, prow, cs, c);
    }
}

// ---------------- fused MLP (8Mx2N warps, ldmatrix A+B) ---------------------
// fp16 mma m16n8k16; 512 threads = 16 warps; 256 rows/CTA.

__device__ __forceinline__ uint32_t s2u(const void* p) {
    return (uint32_t)__cvta_generic_to_shared(p);
}
__device__ __forceinline__ void ldmA(uint32_t* a, const void* p) {
    asm volatile("ldmatrix.sync.aligned.m8n8.x4.shared.b16 {%0,%1,%2,%3}, [%4];"
        : "=r"(a[0]),"=r"(a[1]),"=r"(a[2]),"=r"(a[3]) : "r"(s2u(p)));
}
__device__ __forceinline__ void ldmB4(uint32_t* b, uint32_t saddr) {
    asm volatile("ldmatrix.sync.aligned.m8n8.x4.shared.b16 {%0,%1,%2,%3}, [%4];"
        : "=r"(b[0]),"=r"(b[1]),"=r"(b[2]),"=r"(b[3]) : "r"(saddr));
}
__device__ __forceinline__ void mma16(float* d, const uint32_t* a, const uint32_t* b,
                                      const float* c) {
    asm volatile("mma.sync.aligned.m16n8k16.row.col.f32.f16.f16.f32 "
        "{%0,%1,%2,%3}, {%4,%5,%6,%7}, {%8,%9}, {%10,%11,%12,%13};"
        : "=f"(d[0]),"=f"(d[1]),"=f"(d[2]),"=f"(d[3])
        : "r"(a[0]),"r"(a[1]),"r"(a[2]),"r"(a[3]),
          "r"(b[0]),"r"(b[1]),
          "f"(c[0]),"f"(c[1]),"f"(c[2]),"f"(c[3]));
}

#define SAS 264                     // sA [256 m][264] half (also sH region)
#define SHS_H 136                   // sH [256 m][136] half (inside sA region)
#define AW_HALFS (256*SAS)          // 67584 halfs = 135168 B
#define MLP_SMEM_BYTES (AW_HALFS*2 + 256*SW2S_H*2)   // 204800

__global__ __launch_bounds__(512, 1) void k_mlp(
    const float* __restrict__ feats, float* __restrict__ out) {
    extern __shared__ __half smh[];
    __half* sA  = smh;                       // phase A: A tile; phase B: sH
    __half* sW  = smh + AW_HALFS;            // phase A: W1T; phase B: W2T
    __half* sH  = smh;

    int tid = threadIdx.x;
    int lane = tid & 31, wid = tid >> 5;
    int group = lane >> 2, tg = lane & 3;
    int warpM = wid & 7, warpN = wid >> 3;   // 8 x 2
    int rowbase = warpM * 32;
    int colbase = warpN * 64;
    int m0 = blockIdx.x * 256;

    // ldmatrix-B per-lane tile addressing
    int bg = lane >> 3, br = lane & 7;
    int b_nt_off = (bg >> 1);                // 0/1 : which nt within the pair
    int b_k_off  = (bg & 1) * 8;             // 0/8 : k half

    // stage A tile (256 rows x 256 halfs) from g_y with uint4 loads
    {
        const __half* Yh = (const __half*)g_y;
        #pragma unroll
        for (int k = 0; k < 16; k++) {
            int u = tid + 512*k;             // uint4 index, 8192 total
            int row = u >> 5, cw = (u & 31)*8;
            int gr = m0 + row; if (gr >= NPTS) gr = NPTS - 1;
            uint4 v = *(const uint4*)(Yh + (size_t)gr*CC + cw);
            *(uint4*)&sA[row*SAS + cw] = v;
        }
    }
    // stage prepacked W1T: 4224 uint4
    {
        const uint4* wsrc = (const uint4*)g_w1p;
        uint4* wdst = (uint4*)sW;
        #pragma unroll
        for (int k = 0; k < 9; k++) {
            int u = tid + 512*k;
            if (u < (RR*SWS)/8) wdst[u] = wsrc[u];
        }
    }
    __syncthreads();

    // ---- GEMM1: H[256][128] = A @ W1 ----
    int lrow = lane & 15;
    int lk   = (lane >> 4) * 8;
    {
        uint32_t bp[4];
        #pragma unroll
        for (int j = 0; j < 4; j++)
            bp[j] = s2u(&sW[(colbase + (2*j + b_nt_off)*8 + br)*SWS + b_k_off]);

        float acc[2][8][4];
        #pragma unroll
        for (int mt = 0; mt < 2; mt++)
            #pragma unroll
            for (int nt = 0; nt < 8; nt++)
                #pragma unroll
                for (int q = 0; q < 4; q++) acc[mt][nt][q] = 0.f;

        for (int k0 = 0; k0 < CC; k0 += 16) {
            uint32_t a[2][4];
            #pragma unroll
            for (int mt = 0; mt < 2; mt++)
                ldmA(a[mt], &sA[(rowbase + mt*16 + lrow)*SAS + k0 + lk]);
            uint32_t b[8][2];
            #pragma unroll
            for (int j = 0; j < 4; j++) {
                uint32_t bb[4];
                ldmB4(bb, bp[j] + k0*2);
                b[2*j][0]   = bb[0]; b[2*j][1]   = bb[1];
                b[2*j+1][0] = bb[2]; b[2*j+1][1] = bb[3];
            }
            #pragma unroll
            for (int mt = 0; mt < 2; mt++)
                #pragma unroll
                for (int nt = 0; nt < 8; nt++)
                    mma16(acc[mt][nt], a[mt], b[nt], acc[mt][nt]);
        }
        __syncthreads();   // everyone done reading sA / sW

        // relu -> sH (fp16, reuses sA region)
        #pragma unroll
        for (int mt = 0; mt < 2; mt++)
            #pragma unroll
            for (int nt = 0; nt < 8; nt++) {
                int rl = rowbase + mt*16 + group;
                int cl = colbase + nt*8 + 2*tg;
                __half2 h0 = __floats2half2_rn(fmaxf(acc[mt][nt][0],0.f),
                                               fmaxf(acc[mt][nt][1],0.f));
                __half2 h1 = __floats2half2_rn(fmaxf(acc[mt][nt][2],0.f),
                                               fmaxf(acc[mt][nt][3],0.f));
                *(__half2*)&sH[rl*SHS_H + cl]     = h0;
                *(__half2*)&sH[(rl+8)*SHS_H + cl] = h1;
            }
    }
    // stage prepacked W2T: 4352 uint4
    {
        const uint4* wsrc = (const uint4*)g_w2p;
        uint4* wdst = (uint4*)sW;
        #pragma unroll
        for (int k = 0; k < 9; k++) {
            int u = tid + 512*k;
            if (u < (CC*SW2S_H)/8) wdst[u] = wsrc[u];
        }
    }
    __syncthreads();

    // ---- GEMM2: Z = H @ W2, two 64-col passes per warp ----
    for (int p = 0; p < 2; p++) {
        int cb = warpN*128 + p*64;
        uint32_t bp[4];
        #pragma unroll
        for (int j = 0; j < 4; j++)
            bp[j] = s2u(&sW[(cb + (2*j + b_nt_off)*8 + br)*SW2S_H + b_k_off]);

        float acc2[2][8][4];
        #pragma unroll
        for (int mt = 0; mt < 2; mt++)
            #pragma unroll
            for (int nt = 0; nt < 8; nt++)
                #pragma unroll
                for (int q = 0; q < 4; q++) acc2[mt][nt][q] = 0.f;

        for (int k0 = 0; k0 < RR; k0 += 16) {
            uint32_t a[2][4];
            #pragma unroll
            for (int mt = 0; mt < 2; mt++)
                ldmA(a[mt], &sH[(rowbase + mt*16 + lrow)*SHS_H + k0 + lk]);
            uint32_t b[8][2];
            #pragma unroll
            for (int j = 0; j < 4; j++) {
                uint32_t bb[4];
                ldmB4(bb, bp[j] + k0*2);
                b[2*j][0]   = bb[0]; b[2*j][1]   = bb[1];
                b[2*j+1][0] = bb[2]; b[2*j+1][1] = bb[3];
            }
            #pragma unroll
            for (int mt = 0; mt < 2; mt++)
                #pragma unroll
                for (int nt = 0; nt < 8; nt++)
                    mma16(acc2[mt][nt], a[mt], b[nt], acc2[mt][nt]);
        }

        // epilogue: sigmoid, multiply feats, store
        #pragma unroll
        for (int mt = 0; mt < 2; mt++)
            #pragma unroll
            for (int nt = 0; nt < 8; nt++) {
                int rl = rowbase + mt*16 + group;
                int cl = cb + nt*8 + 2*tg;
                int gi0 = m0 + rl, gi1 = gi0 + 8;
                if (gi0 < NPTS) {
                    float2 f = *(const float2*)(feats + (size_t)gi0*CC + cl);
                    float s0 = 1.f/(1.f + __expf(-acc2[mt][nt][0]));
                    float s1 = 1.f/(1.f + __expf(-acc2[mt][nt][1]));
                    float2 o; o.x = f.x*s0; o.y = f.y*s1;
                    *(float2*)(out + (size_t)gi0*CC + cl) = o;
                }
                if (gi1 < NPTS) {
                    float2 f = *(const float2*)(feats + (size_t)gi1*CC + cl);
                    float s2 = 1.f/(1.f + __expf(-acc2[mt][nt][2]));
                    float s3 = 1.f/(1.f + __expf(-acc2[mt][nt][3]));
                    float2 o; o.x = f.x*s2; o.y = f.y*s3;
                    *(float2*)(out + (size_t)gi1*CC + cl) = o;
                }
            }
    }
}

// ---------------- launch ----------------------------------------------------
extern "C" void kernel_launch(void* const* d_in, const int* in_sizes, int n_in,
                              void* d_out, int out_size) {
    const float* feats  = (const float*)d_in[0];
    const int*   coords = (const int*)d_in[1];
    const float* W1     = (const float*)d_in[2];
    const float* W2     = (const float*)d_in[3];
    float*       out    = (float*)d_out;

    k_init_prepack<<<(VV + 255)/256, 256>>>(W1, W2);
    k_scatter<<<(NPTS + 255)/256, 256>>>(coords);
    k_pool_z<<<2048, 256>>>(feats);

    cudaFuncSetAttribute(k_pool_yx, cudaFuncAttributeMaxDynamicSharedMemorySize,
                         YX_SMEM_BYTES);
    k_pool_yx<<<2048, 512, YX_SMEM_BYTES>>>();

    cudaFuncSetAttribute(k_mlp, cudaFuncAttributeMaxDynamicSharedMemorySize,
                         MLP_SMEM_BYTES);
    int nblk = (NPTS + 255) / 256;   // 391
    k_mlp<<<nblk, 512, MLP_SMEM_BYTES>>>(feats, out);
}